// round 6
// baseline (speedup 1.0000x reference)
#include <cuda_runtime.h>
#include <cuda_bf16.h>
#include <math.h>
#include <stdint.h>
#include <string.h>

#define Bd 4
#define Sd 1024
#define Dd 1024
#define Hd 16
#define DKd 64
#define DFFd 4096
#define Md (Bd * Sd)   // 4096 rows
#define NQKV 3072

// ---------------- scratch (device globals; no runtime allocation) ----------
__device__ float g_x2 [Md * Dd];
__device__ float g_bqkv[NQKV];
__device__ __nv_bfloat16 g_xn_h [Md * Dd],  g_xn_l [Md * Dd];
__device__ __nv_bfloat16 g_xn2_h[Md * Dd],  g_xn2_l[Md * Dd];
__device__ __nv_bfloat16 g_ctx_h[Md * Dd],  g_ctx_l[Md * Dd];
__device__ __nv_bfloat16 g_qkv_h[(size_t)Md * NQKV], g_qkv_l[(size_t)Md * NQKV];
__device__ __nv_bfloat16 g_wqkvT_h[NQKV * Dd], g_wqkvT_l[NQKV * Dd];
__device__ __nv_bfloat16 g_woT_h[Dd * Dd],  g_woT_l[Dd * Dd];
__device__ __nv_bfloat16 g_w1T_h[DFFd * Dd], g_w1T_l[DFFd * Dd];
__device__ __nv_bfloat16 g_w2T_h[Dd * DFFd], g_w2T_l[Dd * DFFd];
__device__ __nv_bfloat16 g_ff_h [(size_t)Md * DFFd], g_ff_l[(size_t)Md * DFFd];

// ---------------- PTX helpers (sm_80-compatible) ----------------------------
__device__ __forceinline__ uint32_t smem_u32(const void* p) {
    uint32_t a;
    asm("{ .reg .u64 t; cvta.to.shared.u64 t, %1; cvt.u32.u64 %0, t; }"
        : "=r"(a) : "l"(p));
    return a;
}
__device__ __forceinline__ void cp16(uint32_t s, const void* g) {
    asm volatile("cp.async.cg.shared.global [%0], [%1], 16;" :: "r"(s), "l"(g));
}
__device__ __forceinline__ void cp_commit() {
    asm volatile("cp.async.commit_group;");
}
template <int N>
__device__ __forceinline__ void cp_wait() {
    asm volatile("cp.async.wait_group %0;" :: "n"(N));
}
__device__ __forceinline__ void ldm4(uint32_t* r, uint32_t a) {
    asm volatile("ldmatrix.sync.aligned.m8n8.x4.shared.b16 {%0,%1,%2,%3}, [%4];"
        : "=r"(r[0]), "=r"(r[1]), "=r"(r[2]), "=r"(r[3]) : "r"(a));
}
__device__ __forceinline__ void ldm4t(uint32_t* r, uint32_t a) {
    asm volatile("ldmatrix.sync.aligned.m8n8.x4.trans.shared.b16 {%0,%1,%2,%3}, [%4];"
        : "=r"(r[0]), "=r"(r[1]), "=r"(r[2]), "=r"(r[3]) : "r"(a));
}
__device__ __forceinline__ void mma_bf16(float* d, const uint32_t* a,
                                         uint32_t b0, uint32_t b1) {
    asm volatile(
        "mma.sync.aligned.m16n8k16.row.col.f32.bf16.bf16.f32 "
        "{%0,%1,%2,%3}, {%4,%5,%6,%7}, {%8,%9}, {%0,%1,%2,%3};"
        : "+f"(d[0]), "+f"(d[1]), "+f"(d[2]), "+f"(d[3])
        : "r"(a[0]), "r"(a[1]), "r"(a[2]), "r"(a[3]), "r"(b0), "r"(b1));
}
__device__ __forceinline__ uint32_t pack_bf2(float a, float b) {
    __nv_bfloat162 t;
    t.x = __float2bfloat16(a); t.y = __float2bfloat16(b);
    uint32_t u; memcpy(&u, &t, 4); return u;
}
__device__ __forceinline__ int st_off(int r, int c16) {
    return r * 128 + ((c16 ^ (r & 7)) << 4);   // swizzled byte offset (128B rows)
}

// ---------------- bias concat ------------------------------------------------
__global__ void concat3(const float* __restrict__ a, const float* __restrict__ b,
                        const float* __restrict__ c, float* __restrict__ o) {
    const int i = blockIdx.x * 256 + threadIdx.x;
    if (i < 1024) o[i] = a[i];
    else if (i < 2048) o[i] = b[i - 1024];
    else if (i < 3072) o[i] = c[i - 2048];
}

// ---------------- LayerNorm (torch-style: ddof=1, eps on std) → bf16 hi/lo -
__global__ void ln_kernel(const float* __restrict__ X,
                          __nv_bfloat16* __restrict__ Yh,
                          __nv_bfloat16* __restrict__ Yl,
                          const float* __restrict__ alpha,
                          const float* __restrict__ beta) {
    __shared__ float red[256];
    __shared__ float s_mean, s_inv;
    const int row = blockIdx.x;
    const int tid = threadIdx.x;
    const float* x = X + (size_t)row * Dd;

    float4 xv = *(const float4*)(x + tid * 4);
    float s = xv.x + xv.y + xv.z + xv.w;
    red[tid] = s; __syncthreads();
    #pragma unroll
    for (int off = 128; off > 0; off >>= 1) {
        if (tid < off) red[tid] += red[tid + off];
        __syncthreads();
    }
    if (tid == 0) s_mean = red[0] * (1.0f / Dd);
    __syncthreads();
    const float mean = s_mean;
    float d0 = xv.x - mean, d1 = xv.y - mean, d2 = xv.z - mean, d3 = xv.w - mean;
    red[tid] = d0 * d0 + d1 * d1 + d2 * d2 + d3 * d3; __syncthreads();
    #pragma unroll
    for (int off = 128; off > 0; off >>= 1) {
        if (tid < off) red[tid] += red[tid + off];
        __syncthreads();
    }
    if (tid == 0) {
        float var = red[0] * (1.0f / (Dd - 1));
        s_inv = alpha[0] / (sqrtf(var) + 1e-6f);
    }
    __syncthreads();
    const float inv = s_inv;
    const float bt  = beta[0];
    float y[4] = {d0 * inv + bt, d1 * inv + bt, d2 * inv + bt, d3 * inv + bt};
    size_t o = (size_t)row * Dd + tid * 4;
    #pragma unroll
    for (int i = 0; i < 4; i++) {
        __nv_bfloat16 h = __float2bfloat16(y[i]);
        Yh[o + i] = h;
        Yl[o + i] = __float2bfloat16(y[i] - __bfloat162float(h));
    }
}

// ---------------- weight transpose + bf16 hi/lo split -----------------------
__global__ void transpose_split(const float* __restrict__ in,
                                __nv_bfloat16* __restrict__ oh,
                                __nv_bfloat16* __restrict__ ol,
                                int R, int C) {
    __shared__ float tile[32][33];
    const int c = blockIdx.x * 32 + threadIdx.x;
    const int r0 = blockIdx.y * 32;
    #pragma unroll
    for (int i = 0; i < 4; i++)
        tile[threadIdx.y + i * 8][threadIdx.x] =
            in[(size_t)(r0 + threadIdx.y + i * 8) * C + c];
    __syncthreads();
    const int rr = r0 + threadIdx.x;
    #pragma unroll
    for (int i = 0; i < 4; i++) {
        const int oc = blockIdx.x * 32 + threadIdx.y + i * 8;
        float v = tile[threadIdx.x][threadIdx.y + i * 8];
        __nv_bfloat16 h = __float2bfloat16(v);
        size_t o = (size_t)oc * R + rr;
        oh[o] = h;
        ol[o] = __float2bfloat16(v - __bfloat162float(h));
    }
}

// ---------------- bf16x3 GEMM via mma.sync, 256x128 tile, BK=64, 2 stages --
// 512 threads, 16 warps (4x4), warp tile 64x32.
// MODE 1: Cf = acc + bias + Rm
// MODE 2: Ch/Cl = bf16_split(relu(acc + bias))
// MODE 3: Ch/Cl = bf16_split(acc + bias)
#define TA_B 32768                    // 256x64 bf16
#define TB_B 16384                    // 128x64 bf16
#define STG_B (2 * TA_B + 2 * TB_B)   // 98304
#define GEMM_SMEM (2 * STG_B)         // 196608

template <int MODE>
__global__ void __launch_bounds__(512, 1)
mma_gemm(const __nv_bfloat16* __restrict__ Ah, const __nv_bfloat16* __restrict__ Al,
         const __nv_bfloat16* __restrict__ Bh, const __nv_bfloat16* __restrict__ Bl,
         const float* __restrict__ bias, const float* __restrict__ Rm,
         float* __restrict__ Cf,
         __nv_bfloat16* __restrict__ Ch, __nv_bfloat16* __restrict__ Cl,
         int M, int N, int K) {
    extern __shared__ char smem[];
    const uint32_t sb = smem_u32(smem);
    const int tid = threadIdx.x;
    const int wid = tid >> 5, lane = tid & 31;
    const int m0 = blockIdx.y * 256;
    const int n0 = blockIdx.x * 128;
    const int wm = (wid >> 2) * 64;
    const int wn = (wid & 3) * 32;

    float acc[4][4][4];
    #pragma unroll
    for (int a = 0; a < 4; a++)
        #pragma unroll
        for (int b = 0; b < 4; b++)
            #pragma unroll
            for (int c = 0; c < 4; c++) acc[a][b][c] = 0.f;

    const int nstg = K >> 6;

    auto load_stage = [&](int t, int s) {
        const int k0 = t << 6;
        const uint32_t st = sb + (uint32_t)s * STG_B;
        #pragma unroll
        for (int i = 0; i < 4; i++) {                 // A: 2048 16B chunks
            const int chunk = tid + i * 512;
            const int r = chunk >> 3, c = chunk & 7;
            const uint32_t so = st + st_off(r, c);
            const size_t ga = (size_t)(m0 + r) * K + k0 + c * 8;
            cp16(so, Ah + ga);
            cp16(so + TA_B, Al + ga);
        }
        #pragma unroll
        for (int i = 0; i < 2; i++) {                 // B: 1024 16B chunks
            const int chunk = tid + i * 512;
            const int r = chunk >> 3, c = chunk & 7;
            const uint32_t so = st + 2 * TA_B + st_off(r, c);
            const size_t gb = (size_t)(n0 + r) * K + k0 + c * 8;
            cp16(so, Bh + gb);
            cp16(so + TB_B, Bl + gb);
        }
        cp_commit();
    };

    load_stage(0, 0);

    const int lrow = lane & 15, lsel = lane >> 4;

    for (int t = 0; t < nstg; t++) {
        const int s = t & 1;
        if (t + 1 < nstg) { load_stage(t + 1, s ^ 1); cp_wait<1>(); }
        else              { cp_wait<0>(); }
        __syncthreads();

        const uint32_t stg = sb + (uint32_t)s * STG_B;
        #pragma unroll
        for (int kk = 0; kk < 4; kk++) {
            uint32_t ah[4][4], al[4][4], bh[2][4], bl[2][4];
            #pragma unroll
            for (int mt = 0; mt < 4; mt++) {
                const uint32_t ad = stg + st_off(wm + mt * 16 + lrow, kk * 2 + lsel);
                ldm4(ah[mt], ad);
                ldm4(al[mt], ad + TA_B);
            }
            #pragma unroll
            for (int g = 0; g < 2; g++) {
                const uint32_t bd = stg + 2 * TA_B +
                                    st_off(wn + g * 16 + lrow, kk * 2 + lsel);
                ldm4(bh[g], bd);
                ldm4(bl[g], bd + TB_B);
            }
            #pragma unroll
            for (int mt = 0; mt < 4; mt++) {
                #pragma unroll
                for (int nt2 = 0; nt2 < 4; nt2++) {
                    const int g = nt2 >> 1, sel = nt2 & 1;
                    mma_bf16(acc[mt][nt2], ah[mt], bh[g][sel], bh[g][sel + 2]);
                    mma_bf16(acc[mt][nt2], ah[mt], bl[g][sel], bl[g][sel + 2]);
                    mma_bf16(acc[mt][nt2], al[mt], bh[g][sel], bh[g][sel + 2]);
                }
            }
        }
        __syncthreads();
    }

    const int er = lane >> 2, ec = (lane & 3) * 2;
    #pragma unroll
    for (int mt = 0; mt < 4; mt++) {
        #pragma unroll
        for (int half = 0; half < 2; half++) {
            const int row = m0 + wm + mt * 16 + er + half * 8;
            #pragma unroll
            for (int nt2 = 0; nt2 < 4; nt2++) {
                const int col = n0 + wn + nt2 * 8 + ec;
                float v0 = acc[mt][nt2][half * 2 + 0] + bias[col];
                float v1 = acc[mt][nt2][half * 2 + 1] + bias[col + 1];
                const size_t o = (size_t)row * N + col;
                if (MODE >= 2) {
                    if (MODE == 2) { v0 = fmaxf(v0, 0.f); v1 = fmaxf(v1, 0.f); }
                    __nv_bfloat16 h0 = __float2bfloat16(v0);
                    __nv_bfloat16 h1 = __float2bfloat16(v1);
                    __nv_bfloat162 hp; hp.x = h0; hp.y = h1;
                    *(__nv_bfloat162*)(Ch + o) = hp;
                    __nv_bfloat162 lp;
                    lp.x = __float2bfloat16(v0 - __bfloat162float(h0));
                    lp.y = __float2bfloat16(v1 - __bfloat162float(h1));
                    *(__nv_bfloat162*)(Cl + o) = lp;
                } else {
                    if (MODE == 1) { v0 += Rm[o]; v1 += Rm[o + 1]; }
                    *(float2*)(Cf + o) = make_float2(v0, v1);
                }
            }
        }
    }
}

// ---------------- tensor-core flash attention (bf16x3 QK and PV) ------------
// reads packed qkv (row stride 3072): q at +0, k at +1024, v at +2048
#define AQ_B  (128 * 128)
#define AKV_B (64 * 128)
#define AT_SMEM (2 * AQ_B + 2 * 4 * AKV_B + Sd * 4)

__global__ void __launch_bounds__(256, 1)
attn_mma(const __nv_bfloat16* __restrict__ QKVh,
         const __nv_bfloat16* __restrict__ QKVl,
         const int* __restrict__ mask,
         __nv_bfloat16* __restrict__ Oh, __nv_bfloat16* __restrict__ Ol) {
    extern __shared__ char smem[];
    const uint32_t sb = smem_u32(smem);
    const uint32_t sQh = sb, sQl = sb + AQ_B;
    int* smask = (int*)(smem + 2 * AQ_B + 2 * 4 * AKV_B);

    const int tid = threadIdx.x;
    const int wid = tid >> 5, lane = tid & 31;
    const int lrow = lane & 15, lsel = lane >> 4;
    const int lam = lane & 3, ldv = lane >> 2;

    const int qb = blockIdx.x, bh = blockIdx.y;
    const int b = bh >> 4, h = bh & 15;
    const size_t baseQ = (size_t)b * Sd * NQKV + h * DKd;
    const size_t baseK = baseQ + 1024;
    const size_t baseV = baseQ + 2048;
    const int qrow0 = qb * 128;

    #pragma unroll
    for (int i = 0; i < 4; i++) {
        const int chunk = tid + i * 256;
        const int r = chunk >> 3, c = chunk & 7;
        const size_t g = baseQ + (size_t)(qrow0 + r) * NQKV + c * 8;
        cp16(sQh + st_off(r, c), QKVh + g);
        cp16(sQl + st_off(r, c), QKVl + g);
    }
    for (int i = tid; i < Sd; i += 256) smask[i] = mask[b * Sd + i];

    auto load_kv = [&](int kb, int s) {
        const uint32_t st = sb + 2 * AQ_B + (uint32_t)s * 4 * AKV_B;
        #pragma unroll
        for (int i = 0; i < 2; i++) {
            const int chunk = tid + i * 256;
            const int r = chunk >> 3, c = chunk & 7;
            const uint32_t so = st_off(r, c);
            const size_t row = (size_t)(kb * 64 + r) * NQKV + c * 8;
            cp16(st + 0 * AKV_B + so, QKVh + baseK + row);
            cp16(st + 1 * AKV_B + so, QKVl + baseK + row);
            cp16(st + 2 * AKV_B + so, QKVh + baseV + row);
            cp16(st + 3 * AKV_B + so, QKVl + baseV + row);
        }
    };

    load_kv(0, 0);
    cp_commit();

    float O[8][4];
    #pragma unroll
    for (int j = 0; j < 8; j++)
        #pragma unroll
        for (int c = 0; c < 4; c++) O[j][c] = 0.f;
    float m0r = -1e30f, m1r = -1e30f, l0r = 0.f, l1r = 0.f;

    const int NKB = Sd / 64;
    for (int kb = 0; kb < NKB; kb++) {
        const int s = kb & 1;
        if (kb + 1 < NKB) { load_kv(kb + 1, s ^ 1); cp_commit(); cp_wait<1>(); }
        else              { cp_wait<0>(); }
        __syncthreads();

        const uint32_t stK = sb + 2 * AQ_B + (uint32_t)s * 4 * AKV_B;
        const uint32_t stV = stK + 2 * AKV_B;

        float Sc[8][4];
        #pragma unroll
        for (int j = 0; j < 8; j++)
            #pragma unroll
            for (int c = 0; c < 4; c++) Sc[j][c] = 0.f;
        #pragma unroll
        for (int kk = 0; kk < 4; kk++) {
            uint32_t qh[4], ql[4], kh[4][4], kl[4][4];
            const uint32_t qa = sQh + st_off(wid * 16 + lrow, kk * 2 + lsel);
            ldm4(qh, qa);
            ldm4(ql, qa + AQ_B);
            #pragma unroll
            for (int g = 0; g < 4; g++) {
                const uint32_t kd = stK + st_off(g * 16 + lrow, kk * 2 + lsel);
                ldm4(kh[g], kd);
                ldm4(kl[g], kd + AKV_B);
            }
            #pragma unroll
            for (int j = 0; j < 8; j++) {
                const int g = j >> 1, sel = j & 1;
                mma_bf16(Sc[j], qh, kh[g][sel], kh[g][sel + 2]);
                mma_bf16(Sc[j], qh, kl[g][sel], kl[g][sel + 2]);
                mma_bf16(Sc[j], ql, kh[g][sel], kh[g][sel + 2]);
            }
        }

        #pragma unroll
        for (int j = 0; j < 8; j++) {
            const int col = kb * 64 + j * 8 + lam * 2;
            const int mk0 = smask[col], mk1 = smask[col + 1];
            #pragma unroll
            for (int c = 0; c < 4; c++) Sc[j][c] *= 0.125f;
            if (mk0 == 0) { Sc[j][0] = -1e9f; Sc[j][2] = -1e9f; }
            if (mk1 == 0) { Sc[j][1] = -1e9f; Sc[j][3] = -1e9f; }
        }

        float mx0 = -1e30f, mx1 = -1e30f;
        #pragma unroll
        for (int j = 0; j < 8; j++) {
            mx0 = fmaxf(mx0, fmaxf(Sc[j][0], Sc[j][1]));
            mx1 = fmaxf(mx1, fmaxf(Sc[j][2], Sc[j][3]));
        }
        mx0 = fmaxf(mx0, __shfl_xor_sync(0xffffffffu, mx0, 1));
        mx0 = fmaxf(mx0, __shfl_xor_sync(0xffffffffu, mx0, 2));
        mx1 = fmaxf(mx1, __shfl_xor_sync(0xffffffffu, mx1, 1));
        mx1 = fmaxf(mx1, __shfl_xor_sync(0xffffffffu, mx1, 2));
        const float nm0 = fmaxf(m0r, mx0), nm1 = fmaxf(m1r, mx1);
        const float sf0 = __expf(m0r - nm0), sf1 = __expf(m1r - nm1);
        m0r = nm0; m1r = nm1;
        l0r *= sf0; l1r *= sf1;

        uint32_t pah[4][4], pal[4][4];
        #pragma unroll
        for (int j = 0; j < 8; j++) {
            float p0 = __expf(Sc[j][0] - nm0);
            float p1 = __expf(Sc[j][1] - nm0);
            float p2 = __expf(Sc[j][2] - nm1);
            float p3 = __expf(Sc[j][3] - nm1);
            l0r += p0 + p1; l1r += p2 + p3;
            const int t = j >> 1, hi = j & 1;
            const uint32_t h01 = pack_bf2(p0, p1);
            const uint32_t h23 = pack_bf2(p2, p3);
            pah[t][hi * 2 + 0] = h01;
            pah[t][hi * 2 + 1] = h23;
            __nv_bfloat162 b01, b23;
            memcpy(&b01, &h01, 4); memcpy(&b23, &h23, 4);
            pal[t][hi * 2 + 0] = pack_bf2(p0 - __bfloat162float(b01.x),
                                          p1 - __bfloat162float(b01.y));
            pal[t][hi * 2 + 1] = pack_bf2(p2 - __bfloat162float(b23.x),
                                          p3 - __bfloat162float(b23.y));
        }

        #pragma unroll
        for (int j = 0; j < 8; j++) {
            O[j][0] *= sf0; O[j][1] *= sf0;
            O[j][2] *= sf1; O[j][3] *= sf1;
        }

        #pragma unroll
        for (int t = 0; t < 4; t++) {
            #pragma unroll
            for (int jo = 0; jo < 4; jo++) {
                uint32_t vh[4], vl[4];
                const uint32_t vd = stV + st_off(t * 16 + lrow, jo * 2 + lsel);
                ldm4t(vh, vd);
                ldm4t(vl, vd + AKV_B);
                mma_bf16(O[jo * 2 + 0], pah[t], vh[0], vh[1]);
                mma_bf16(O[jo * 2 + 1], pah[t], vh[2], vh[3]);
                mma_bf16(O[jo * 2 + 0], pah[t], vl[0], vl[1]);
                mma_bf16(O[jo * 2 + 1], pah[t], vl[2], vl[3]);
                mma_bf16(O[jo * 2 + 0], pal[t], vh[0], vh[1]);
                mma_bf16(O[jo * 2 + 1], pal[t], vh[2], vh[3]);
            }
        }
        __syncthreads();
    }

    l0r += __shfl_xor_sync(0xffffffffu, l0r, 1);
    l0r += __shfl_xor_sync(0xffffffffu, l0r, 2);
    l1r += __shfl_xor_sync(0xffffffffu, l1r, 1);
    l1r += __shfl_xor_sync(0xffffffffu, l1r, 2);
    const float inv0 = 1.0f / l0r, inv1 = 1.0f / l1r;

    const int row0 = qrow0 + wid * 16 + ldv;
    #pragma unroll
    for (int jn = 0; jn < 8; jn++) {
        const int col = h * DKd + jn * 8 + lam * 2;
        #pragma unroll
        for (int half = 0; half < 2; half++) {
            const float inv = half ? inv1 : inv0;
            const float v0 = O[jn][half * 2 + 0] * inv;
            const float v1 = O[jn][half * 2 + 1] * inv;
            const size_t o = (size_t)b * Sd * Dd +
                             (size_t)(row0 + half * 8) * Dd + col;
            __nv_bfloat16 h0 = __float2bfloat16(v0);
            __nv_bfloat16 h1 = __float2bfloat16(v1);
            __nv_bfloat162 hp; hp.x = h0; hp.y = h1;
            *(__nv_bfloat162*)(Oh + o) = hp;
            __nv_bfloat162 lp;
            lp.x = __float2bfloat16(v0 - __bfloat162float(h0));
            lp.y = __float2bfloat16(v1 - __bfloat162float(h1));
            *(__nv_bfloat162*)(Ol + o) = lp;
        }
    }
}

// ---------------- orchestration --------------------------------------------
extern "C" void kernel_launch(void* const* d_in, const int* in_sizes, int n_in,
                              void* d_out, int out_size) {
    const float* x      = (const float*)d_in[0];
    const int*   mask   = (const int*)  d_in[1];
    const float* wq     = (const float*)d_in[2];
    const float* bq     = (const float*)d_in[3];
    const float* wk     = (const float*)d_in[4];
    const float* bk     = (const float*)d_in[5];
    const float* wv     = (const float*)d_in[6];
    const float* bv     = (const float*)d_in[7];
    const float* wo     = (const float*)d_in[8];
    const float* bo     = (const float*)d_in[9];
    const float* w1     = (const float*)d_in[10];
    const float* b1     = (const float*)d_in[11];
    const float* w2     = (const float*)d_in[12];
    const float* b2     = (const float*)d_in[13];
    const float* alpha1 = (const float*)d_in[14];
    const float* beta1  = (const float*)d_in[15];
    const float* alpha2 = (const float*)d_in[16];
    const float* beta2  = (const float*)d_in[17];
    float* out = (float*)d_out;

    float *x2, *bqkv;
    __nv_bfloat16 *xn_h, *xn_l, *xn2_h, *xn2_l, *ctx_h, *ctx_l;
    __nv_bfloat16 *qkv_h, *qkv_l, *wqkvT_h, *wqkvT_l;
    __nv_bfloat16 *woT_h, *woT_l, *w1T_h, *w1T_l, *w2T_h, *w2T_l, *ff_h, *ff_l;
    cudaGetSymbolAddress((void**)&x2, g_x2);
    cudaGetSymbolAddress((void**)&bqkv, g_bqkv);
    cudaGetSymbolAddress((void**)&xn_h, g_xn_h);   cudaGetSymbolAddress((void**)&xn_l, g_xn_l);
    cudaGetSymbolAddress((void**)&xn2_h, g_xn2_h); cudaGetSymbolAddress((void**)&xn2_l, g_xn2_l);
    cudaGetSymbolAddress((void**)&ctx_h, g_ctx_h); cudaGetSymbolAddress((void**)&ctx_l, g_ctx_l);
    cudaGetSymbolAddress((void**)&qkv_h, g_qkv_h); cudaGetSymbolAddress((void**)&qkv_l, g_qkv_l);
    cudaGetSymbolAddress((void**)&wqkvT_h, g_wqkvT_h);
    cudaGetSymbolAddress((void**)&wqkvT_l, g_wqkvT_l);
    cudaGetSymbolAddress((void**)&woT_h, g_woT_h); cudaGetSymbolAddress((void**)&woT_l, g_woT_l);
    cudaGetSymbolAddress((void**)&w1T_h, g_w1T_h); cudaGetSymbolAddress((void**)&w1T_l, g_w1T_l);
    cudaGetSymbolAddress((void**)&w2T_h, g_w2T_h); cudaGetSymbolAddress((void**)&w2T_l, g_w2T_l);
    cudaGetSymbolAddress((void**)&ff_h, g_ff_h);   cudaGetSymbolAddress((void**)&ff_l, g_ff_l);

    cudaFuncSetAttribute(mma_gemm<1>, cudaFuncAttributeMaxDynamicSharedMemorySize, GEMM_SMEM);
    cudaFuncSetAttribute(mma_gemm<2>, cudaFuncAttributeMaxDynamicSharedMemorySize, GEMM_SMEM);
    cudaFuncSetAttribute(mma_gemm<3>, cudaFuncAttributeMaxDynamicSharedMemorySize, GEMM_SMEM);
    cudaFuncSetAttribute(attn_mma, cudaFuncAttributeMaxDynamicSharedMemorySize, AT_SMEM);

    dim3 tb(32, 8);
    // launches 0-4 (so that launch index 5 = QKV GEMM gets profiled)
    concat3<<<12, 256>>>(bq, bk, bv, bqkv);
    transpose_split<<<dim3(Dd / 32, Dd / 32), tb>>>(wq, wqkvT_h + 0 * Dd * Dd,
                                                    wqkvT_l + 0 * Dd * Dd, Dd, Dd);
    transpose_split<<<dim3(Dd / 32, Dd / 32), tb>>>(wk, wqkvT_h + 1 * Dd * Dd,
                                                    wqkvT_l + 1 * Dd * Dd, Dd, Dd);
    transpose_split<<<dim3(Dd / 32, Dd / 32), tb>>>(wv, wqkvT_h + 2 * Dd * Dd,
                                                    wqkvT_l + 2 * Dd * Dd, Dd, Dd);
    ln_kernel<<<Md, 256>>>(x, xn_h, xn_l, alpha1, beta1);

    // launch 5: fused QKV projection -> packed qkv (hi/lo), N=3072
    mma_gemm<3><<<dim3(NQKV / 128, Md / 256), 512, GEMM_SMEM>>>(
        xn_h, xn_l, wqkvT_h, wqkvT_l, bqkv, nullptr, nullptr,
        qkv_h, qkv_l, Md, NQKV, Dd);

    transpose_split<<<dim3(Dd / 32, Dd / 32), tb>>>(wo, woT_h, woT_l, Dd, Dd);

    // attention -> ctx (hi/lo)
    attn_mma<<<dim3(Sd / 128, Bd * Hd), 256, AT_SMEM>>>(qkv_h, qkv_l, mask,
                                                        ctx_h, ctx_l);

    // O projection + residual -> x2 (f32)
    mma_gemm<1><<<dim3(Dd / 128, Md / 256), 512, GEMM_SMEM>>>(
        ctx_h, ctx_l, woT_h, woT_l, bo, x, x2, nullptr, nullptr, Md, Dd, Dd);

    // LN2 -> xn2 (hi/lo)
    ln_kernel<<<Md, 256>>>(x2, xn2_h, xn2_l, alpha2, beta2);

    transpose_split<<<dim3(DFFd / 32, Dd / 32), tb>>>(w1, w1T_h, w1T_l, Dd, DFFd);

    // FF1 + ReLU -> ff (hi/lo)
    mma_gemm<2><<<dim3(DFFd / 128, Md / 256), 512, GEMM_SMEM>>>(
        xn2_h, xn2_l, w1T_h, w1T_l, b1, nullptr, nullptr, ff_h, ff_l, Md, DFFd, Dd);

    transpose_split<<<dim3(Dd / 32, DFFd / 32), tb>>>(w2, w2T_h, w2T_l, DFFd, Dd);

    // FF2 + residual -> out (f32)
    mma_gemm<1><<<dim3(Dd / 128, Md / 256), 512, GEMM_SMEM>>>(
        ff_h, ff_l, w2T_h, w2T_l, b2, x2, out, nullptr, nullptr, Md, Dd, DFFd);
}

// round 8
// speedup vs baseline: 1.6005x; 1.6005x over previous
#include <cuda_runtime.h>
#include <cuda_bf16.h>
#include <math.h>
#include <stdint.h>
#include <string.h>

#define Bd 4
#define Sd 1024
#define Dd 1024
#define Hd 16
#define DKd 64
#define DFFd 4096
#define Md (Bd * Sd)   // 4096 rows
#define NQKV 3072

// ---------------- scratch (device globals; no runtime allocation) ----------
__device__ float g_x2 [Md * Dd];
__device__ float g_bqkv[NQKV];
__device__ __nv_bfloat16 g_xn_h [Md * Dd],  g_xn_l [Md * Dd];
__device__ __nv_bfloat16 g_xn2_h[Md * Dd],  g_xn2_l[Md * Dd];
__device__ __nv_bfloat16 g_ctx_h[Md * Dd],  g_ctx_l[Md * Dd];
__device__ __nv_bfloat16 g_qkv_h[(size_t)Md * NQKV], g_qkv_l[(size_t)Md * NQKV];
__device__ __nv_bfloat16 g_wqkvT_h[NQKV * Dd], g_wqkvT_l[NQKV * Dd];
__device__ __nv_bfloat16 g_woT_h[Dd * Dd],  g_woT_l[Dd * Dd];
__device__ __nv_bfloat16 g_w1T_h[DFFd * Dd], g_w1T_l[DFFd * Dd];
__device__ __nv_bfloat16 g_w2T_h[Dd * DFFd], g_w2T_l[Dd * DFFd];
__device__ __nv_bfloat16 g_ff_h [(size_t)Md * DFFd], g_ff_l[(size_t)Md * DFFd];

// ---------------- PTX helpers (sm_80-compatible) ----------------------------
__device__ __forceinline__ uint32_t smem_u32(const void* p) {
    uint32_t a;
    asm("{ .reg .u64 t; cvta.to.shared.u64 t, %1; cvt.u32.u64 %0, t; }"
        : "=r"(a) : "l"(p));
    return a;
}
__device__ __forceinline__ void cp16(uint32_t s, const void* g) {
    asm volatile("cp.async.cg.shared.global [%0], [%1], 16;" :: "r"(s), "l"(g));
}
__device__ __forceinline__ void cp_commit() {
    asm volatile("cp.async.commit_group;");
}
template <int N>
__device__ __forceinline__ void cp_wait() {
    asm volatile("cp.async.wait_group %0;" :: "n"(N));
}
__device__ __forceinline__ void ldm4(uint32_t* r, uint32_t a) {
    asm volatile("ldmatrix.sync.aligned.m8n8.x4.shared.b16 {%0,%1,%2,%3}, [%4];"
        : "=r"(r[0]), "=r"(r[1]), "=r"(r[2]), "=r"(r[3]) : "r"(a));
}
__device__ __forceinline__ void ldm4t(uint32_t* r, uint32_t a) {
    asm volatile("ldmatrix.sync.aligned.m8n8.x4.trans.shared.b16 {%0,%1,%2,%3}, [%4];"
        : "=r"(r[0]), "=r"(r[1]), "=r"(r[2]), "=r"(r[3]) : "r"(a));
}
__device__ __forceinline__ void mma_bf16(float* d, const uint32_t* a,
                                         uint32_t b0, uint32_t b1) {
    asm volatile(
        "mma.sync.aligned.m16n8k16.row.col.f32.bf16.bf16.f32 "
        "{%0,%1,%2,%3}, {%4,%5,%6,%7}, {%8,%9}, {%0,%1,%2,%3};"
        : "+f"(d[0]), "+f"(d[1]), "+f"(d[2]), "+f"(d[3])
        : "r"(a[0]), "r"(a[1]), "r"(a[2]), "r"(a[3]), "r"(b0), "r"(b1));
}
__device__ __forceinline__ uint32_t pack_bf2(float a, float b) {
    __nv_bfloat162 t;
    t.x = __float2bfloat16(a); t.y = __float2bfloat16(b);
    uint32_t u; memcpy(&u, &t, 4); return u;
}
__device__ __forceinline__ int st_off(int r, int c16) {
    return r * 128 + ((c16 ^ (r & 7)) << 4);   // swizzled byte offset (128B rows)
}

// ---------------- bias concat ------------------------------------------------
__global__ void concat3(const float* __restrict__ a, const float* __restrict__ b,
                        const float* __restrict__ c, float* __restrict__ o) {
    const int i = blockIdx.x * 256 + threadIdx.x;
    if (i < 1024) o[i] = a[i];
    else if (i < 2048) o[i] = b[i - 1024];
    else if (i < 3072) o[i] = c[i - 2048];
}

// ---------------- LayerNorm (torch-style: ddof=1, eps on std) → bf16 hi/lo -
__global__ void ln_kernel(const float* __restrict__ X,
                          __nv_bfloat16* __restrict__ Yh,
                          __nv_bfloat16* __restrict__ Yl,
                          const float* __restrict__ alpha,
                          const float* __restrict__ beta) {
    __shared__ float red[256];
    __shared__ float s_mean, s_inv;
    const int row = blockIdx.x;
    const int tid = threadIdx.x;
    const float* x = X + (size_t)row * Dd;

    float4 xv = *(const float4*)(x + tid * 4);
    float s = xv.x + xv.y + xv.z + xv.w;
    red[tid] = s; __syncthreads();
    #pragma unroll
    for (int off = 128; off > 0; off >>= 1) {
        if (tid < off) red[tid] += red[tid + off];
        __syncthreads();
    }
    if (tid == 0) s_mean = red[0] * (1.0f / Dd);
    __syncthreads();
    const float mean = s_mean;
    float d0 = xv.x - mean, d1 = xv.y - mean, d2 = xv.z - mean, d3 = xv.w - mean;
    red[tid] = d0 * d0 + d1 * d1 + d2 * d2 + d3 * d3; __syncthreads();
    #pragma unroll
    for (int off = 128; off > 0; off >>= 1) {
        if (tid < off) red[tid] += red[tid + off];
        __syncthreads();
    }
    if (tid == 0) {
        float var = red[0] * (1.0f / (Dd - 1));
        s_inv = alpha[0] / (sqrtf(var) + 1e-6f);
    }
    __syncthreads();
    const float inv = s_inv;
    const float bt  = beta[0];
    float y[4] = {d0 * inv + bt, d1 * inv + bt, d2 * inv + bt, d3 * inv + bt};
    size_t o = (size_t)row * Dd + tid * 4;
    #pragma unroll
    for (int i = 0; i < 4; i++) {
        __nv_bfloat16 h = __float2bfloat16(y[i]);
        Yh[o + i] = h;
        Yl[o + i] = __float2bfloat16(y[i] - __bfloat162float(h));
    }
}

// ---------------- weight transpose + bf16 hi/lo split -----------------------
__global__ void transpose_split(const float* __restrict__ in,
                                __nv_bfloat16* __restrict__ oh,
                                __nv_bfloat16* __restrict__ ol,
                                int R, int C) {
    __shared__ float tile[32][33];
    const int c = blockIdx.x * 32 + threadIdx.x;
    const int r0 = blockIdx.y * 32;
    #pragma unroll
    for (int i = 0; i < 4; i++)
        tile[threadIdx.y + i * 8][threadIdx.x] =
            in[(size_t)(r0 + threadIdx.y + i * 8) * C + c];
    __syncthreads();
    const int rr = r0 + threadIdx.x;
    #pragma unroll
    for (int i = 0; i < 4; i++) {
        const int oc = blockIdx.x * 32 + threadIdx.y + i * 8;
        float v = tile[threadIdx.x][threadIdx.y + i * 8];
        __nv_bfloat16 h = __float2bfloat16(v);
        size_t o = (size_t)oc * R + rr;
        oh[o] = h;
        ol[o] = __float2bfloat16(v - __bfloat162float(h));
    }
}

// ---------------- bf16x3 GEMM, 128x128 tile, BK=64, 3-stage cp.async -------
// 256 threads, 8 warps (2x4), warp tile 64x32. Pass-outer mma ordering
// (RAW distance 16) to avoid accumulator dependency stalls.
// MODE 1: Cf = acc + bias + Rm
// MODE 2: Ch/Cl = bf16_split(relu(acc + bias))
// MODE 3: Ch/Cl = bf16_split(acc + bias)
#define TILE_B 16384
#define STAGE_B (4 * TILE_B)          // Ah, Al, Bh, Bl
#define GEMM_SMEM (3 * STAGE_B)       // 196608

template <int MODE>
__global__ void __launch_bounds__(256, 1)
mma_gemm(const __nv_bfloat16* __restrict__ Ah, const __nv_bfloat16* __restrict__ Al,
         const __nv_bfloat16* __restrict__ Bh, const __nv_bfloat16* __restrict__ Bl,
         const float* __restrict__ bias, const float* __restrict__ Rm,
         float* __restrict__ Cf,
         __nv_bfloat16* __restrict__ Ch, __nv_bfloat16* __restrict__ Cl,
         int M, int N, int K) {
    extern __shared__ char smem[];
    const uint32_t sb = smem_u32(smem);
    const int tid = threadIdx.x;
    const int wid = tid >> 5, lane = tid & 31;
    const int m0 = blockIdx.y * 128;
    const int n0 = blockIdx.x * 128;
    const int wm = (wid >> 2) * 64;
    const int wn = (wid & 3) * 32;

    float acc[4][4][4];
    #pragma unroll
    for (int a = 0; a < 4; a++)
        #pragma unroll
        for (int b = 0; b < 4; b++)
            #pragma unroll
            for (int c = 0; c < 4; c++) acc[a][b][c] = 0.f;

    const int nstg = K >> 6;

    auto load_stage = [&](int t, int s) {
        const int k0 = t << 6;
        #pragma unroll
        for (int i = 0; i < 4; i++) {
            const int chunk = tid + i * 256;
            const int r = chunk >> 3, c = chunk & 7;
            const uint32_t so = sb + (uint32_t)s * STAGE_B + st_off(r, c);
            const size_t ga = (size_t)(m0 + r) * K + k0 + c * 8;
            const size_t gb = (size_t)(n0 + r) * K + k0 + c * 8;
            cp16(so + 0 * TILE_B, Ah + ga);
            cp16(so + 1 * TILE_B, Al + ga);
            cp16(so + 2 * TILE_B, Bh + gb);
            cp16(so + 3 * TILE_B, Bl + gb);
        }
        cp_commit();
    };

    load_stage(0, 0);
    load_stage(1, 1);

    const int lrow = lane & 15, lsel = lane >> 4;

    int s = 0;
    for (int t = 0; t < nstg; t++) {
        if (t + 2 < nstg) {
            int s2 = s + 2; if (s2 >= 3) s2 -= 3;
            load_stage(t + 2, s2);
            cp_wait<2>();
        } else if (t + 1 < nstg) {
            cp_wait<1>();
        } else {
            cp_wait<0>();
        }
        __syncthreads();

        const uint32_t stg = sb + (uint32_t)s * STAGE_B;
        #pragma unroll
        for (int kk = 0; kk < 4; kk++) {
            uint32_t ah[4][4], al[4][4], bh[2][4], bl[2][4];
            #pragma unroll
            for (int mt = 0; mt < 4; mt++) {
                const uint32_t ad = stg + st_off(wm + mt * 16 + lrow, kk * 2 + lsel);
                ldm4(ah[mt], ad);
                ldm4(al[mt], ad + TILE_B);
            }
            #pragma unroll
            for (int g = 0; g < 2; g++) {
                const uint32_t bd = stg + 2 * TILE_B +
                                    st_off(wn + g * 16 + lrow, kk * 2 + lsel);
                ldm4(bh[g], bd);
                ldm4(bl[g], bd + TILE_B);
            }
            // pass-outer: RAW distance 16 mmas per accumulator
            #pragma unroll
            for (int mt = 0; mt < 4; mt++)
                #pragma unroll
                for (int nt2 = 0; nt2 < 4; nt2++) {
                    const int g = nt2 >> 1, sel = nt2 & 1;
                    mma_bf16(acc[mt][nt2], ah[mt], bh[g][sel], bh[g][sel + 2]);
                }
            #pragma unroll
            for (int mt = 0; mt < 4; mt++)
                #pragma unroll
                for (int nt2 = 0; nt2 < 4; nt2++) {
                    const int g = nt2 >> 1, sel = nt2 & 1;
                    mma_bf16(acc[mt][nt2], ah[mt], bl[g][sel], bl[g][sel + 2]);
                }
            #pragma unroll
            for (int mt = 0; mt < 4; mt++)
                #pragma unroll
                for (int nt2 = 0; nt2 < 4; nt2++) {
                    const int g = nt2 >> 1, sel = nt2 & 1;
                    mma_bf16(acc[mt][nt2], al[mt], bh[g][sel], bh[g][sel + 2]);
                }
        }
        __syncthreads();
        if (++s >= 3) s = 0;
    }

    const int er = lane >> 2, ec = (lane & 3) * 2;
    #pragma unroll
    for (int mt = 0; mt < 4; mt++) {
        #pragma unroll
        for (int half = 0; half < 2; half++) {
            const int row = m0 + wm + mt * 16 + er + half * 8;
            #pragma unroll
            for (int nt2 = 0; nt2 < 4; nt2++) {
                const int col = n0 + wn + nt2 * 8 + ec;
                float v0 = acc[mt][nt2][half * 2 + 0] + bias[col];
                float v1 = acc[mt][nt2][half * 2 + 1] + bias[col + 1];
                const size_t o = (size_t)row * N + col;
                if (MODE >= 2) {
                    if (MODE == 2) { v0 = fmaxf(v0, 0.f); v1 = fmaxf(v1, 0.f); }
                    __nv_bfloat16 h0 = __float2bfloat16(v0);
                    __nv_bfloat16 h1 = __float2bfloat16(v1);
                    __nv_bfloat162 hp; hp.x = h0; hp.y = h1;
                    *(__nv_bfloat162*)(Ch + o) = hp;
                    __nv_bfloat162 lp;
                    lp.x = __float2bfloat16(v0 - __bfloat162float(h0));
                    lp.y = __float2bfloat16(v1 - __bfloat162float(h1));
                    *(__nv_bfloat162*)(Cl + o) = lp;
                } else {
                    if (MODE == 1) { v0 += Rm[o]; v1 += Rm[o + 1]; }
                    *(float2*)(Cf + o) = make_float2(v0, v1);
                }
            }
        }
    }
}

// ---------------- tensor-core flash attention (bf16x3 QK and PV) ------------
// reads packed qkv (row stride 3072): q at +0, k at +1024, v at +2048
#define AQ_B  (128 * 128)
#define AKV_B (64 * 128)
#define AT_SMEM (2 * AQ_B + 2 * 4 * AKV_B + Sd * 4)

__global__ void __launch_bounds__(256, 1)
attn_mma(const __nv_bfloat16* __restrict__ QKVh,
         const __nv_bfloat16* __restrict__ QKVl,
         const int* __restrict__ mask,
         __nv_bfloat16* __restrict__ Oh, __nv_bfloat16* __restrict__ Ol) {
    extern __shared__ char smem[];
    const uint32_t sb = smem_u32(smem);
    const uint32_t sQh = sb, sQl = sb + AQ_B;
    int* smask = (int*)(smem + 2 * AQ_B + 2 * 4 * AKV_B);

    const int tid = threadIdx.x;
    const int wid = tid >> 5, lane = tid & 31;
    const int lrow = lane & 15, lsel = lane >> 4;
    const int lam = lane & 3, ldv = lane >> 2;

    const int qb = blockIdx.x, bh = blockIdx.y;
    const int b = bh >> 4, h = bh & 15;
    const size_t baseQ = (size_t)b * Sd * NQKV + h * DKd;
    const size_t baseK = baseQ + 1024;
    const size_t baseV = baseQ + 2048;
    const int qrow0 = qb * 128;

    #pragma unroll
    for (int i = 0; i < 4; i++) {
        const int chunk = tid + i * 256;
        const int r = chunk >> 3, c = chunk & 7;
        const size_t g = baseQ + (size_t)(qrow0 + r) * NQKV + c * 8;
        cp16(sQh + st_off(r, c), QKVh + g);
        cp16(sQl + st_off(r, c), QKVl + g);
    }
    for (int i = tid; i < Sd; i += 256) smask[i] = mask[b * Sd + i];

    auto load_kv = [&](int kb, int s) {
        const uint32_t st = sb + 2 * AQ_B + (uint32_t)s * 4 * AKV_B;
        #pragma unroll
        for (int i = 0; i < 2; i++) {
            const int chunk = tid + i * 256;
            const int r = chunk >> 3, c = chunk & 7;
            const uint32_t so = st_off(r, c);
            const size_t row = (size_t)(kb * 64 + r) * NQKV + c * 8;
            cp16(st + 0 * AKV_B + so, QKVh + baseK + row);
            cp16(st + 1 * AKV_B + so, QKVl + baseK + row);
            cp16(st + 2 * AKV_B + so, QKVh + baseV + row);
            cp16(st + 3 * AKV_B + so, QKVl + baseV + row);
        }
    };

    load_kv(0, 0);
    cp_commit();

    float O[8][4];
    #pragma unroll
    for (int j = 0; j < 8; j++)
        #pragma unroll
        for (int c = 0; c < 4; c++) O[j][c] = 0.f;
    float m0r = -1e30f, m1r = -1e30f, l0r = 0.f, l1r = 0.f;

    const int NKB = Sd / 64;
    for (int kb = 0; kb < NKB; kb++) {
        const int s = kb & 1;
        if (kb + 1 < NKB) { load_kv(kb + 1, s ^ 1); cp_commit(); cp_wait<1>(); }
        else              { cp_wait<0>(); }
        __syncthreads();

        const uint32_t stK = sb + 2 * AQ_B + (uint32_t)s * 4 * AKV_B;
        const uint32_t stV = stK + 2 * AKV_B;

        float Sc[8][4];
        #pragma unroll
        for (int j = 0; j < 8; j++)
            #pragma unroll
            for (int c = 0; c < 4; c++) Sc[j][c] = 0.f;
        #pragma unroll
        for (int kk = 0; kk < 4; kk++) {
            uint32_t qh[4], ql[4], kh[4][4], kl[4][4];
            const uint32_t qa = sQh + st_off(wid * 16 + lrow, kk * 2 + lsel);
            ldm4(qh, qa);
            ldm4(ql, qa + AQ_B);
            #pragma unroll
            for (int g = 0; g < 4; g++) {
                const uint32_t kd = stK + st_off(g * 16 + lrow, kk * 2 + lsel);
                ldm4(kh[g], kd);
                ldm4(kl[g], kd + AKV_B);
            }
            // pass-outer: RAW distance 8 per Sc[j]
            #pragma unroll
            for (int j = 0; j < 8; j++) {
                const int g = j >> 1, sel = j & 1;
                mma_bf16(Sc[j], qh, kh[g][sel], kh[g][sel + 2]);
            }
            #pragma unroll
            for (int j = 0; j < 8; j++) {
                const int g = j >> 1, sel = j & 1;
                mma_bf16(Sc[j], qh, kl[g][sel], kl[g][sel + 2]);
            }
            #pragma unroll
            for (int j = 0; j < 8; j++) {
                const int g = j >> 1, sel = j & 1;
                mma_bf16(Sc[j], ql, kh[g][sel], kh[g][sel + 2]);
            }
        }

        #pragma unroll
        for (int j = 0; j < 8; j++) {
            const int col = kb * 64 + j * 8 + lam * 2;
            const int mk0 = smask[col], mk1 = smask[col + 1];
            #pragma unroll
            for (int c = 0; c < 4; c++) Sc[j][c] *= 0.125f;
            if (mk0 == 0) { Sc[j][0] = -1e9f; Sc[j][2] = -1e9f; }
            if (mk1 == 0) { Sc[j][1] = -1e9f; Sc[j][3] = -1e9f; }
        }

        float mx0 = -1e30f, mx1 = -1e30f;
        #pragma unroll
        for (int j = 0; j < 8; j++) {
            mx0 = fmaxf(mx0, fmaxf(Sc[j][0], Sc[j][1]));
            mx1 = fmaxf(mx1, fmaxf(Sc[j][2], Sc[j][3]));
        }
        mx0 = fmaxf(mx0, __shfl_xor_sync(0xffffffffu, mx0, 1));
        mx0 = fmaxf(mx0, __shfl_xor_sync(0xffffffffu, mx0, 2));
        mx1 = fmaxf(mx1, __shfl_xor_sync(0xffffffffu, mx1, 1));
        mx1 = fmaxf(mx1, __shfl_xor_sync(0xffffffffu, mx1, 2));
        const float nm0 = fmaxf(m0r, mx0), nm1 = fmaxf(m1r, mx1);
        const float sf0 = __expf(m0r - nm0), sf1 = __expf(m1r - nm1);
        m0r = nm0; m1r = nm1;
        l0r *= sf0; l1r *= sf1;

        uint32_t pah[4][4], pal[4][4];
        #pragma unroll
        for (int j = 0; j < 8; j++) {
            float p0 = __expf(Sc[j][0] - nm0);
            float p1 = __expf(Sc[j][1] - nm0);
            float p2 = __expf(Sc[j][2] - nm1);
            float p3 = __expf(Sc[j][3] - nm1);
            l0r += p0 + p1; l1r += p2 + p3;
            const int t = j >> 1, hi = j & 1;
            const uint32_t h01 = pack_bf2(p0, p1);
            const uint32_t h23 = pack_bf2(p2, p3);
            pah[t][hi * 2 + 0] = h01;
            pah[t][hi * 2 + 1] = h23;
            __nv_bfloat162 b01, b23;
            memcpy(&b01, &h01, 4); memcpy(&b23, &h23, 4);
            pal[t][hi * 2 + 0] = pack_bf2(p0 - __bfloat162float(b01.x),
                                          p1 - __bfloat162float(b01.y));
            pal[t][hi * 2 + 1] = pack_bf2(p2 - __bfloat162float(b23.x),
                                          p3 - __bfloat162float(b23.y));
        }

        #pragma unroll
        for (int j = 0; j < 8; j++) {
            O[j][0] *= sf0; O[j][1] *= sf0;
            O[j][2] *= sf1; O[j][3] *= sf1;
        }

        // ---- O += P V, per k16-tile t: load all V frags, then pass-outer ----
        #pragma unroll
        for (int t = 0; t < 4; t++) {
            uint32_t vh[4][4], vl[4][4];
            #pragma unroll
            for (int jo = 0; jo < 4; jo++) {
                const uint32_t vd = stV + st_off(t * 16 + lrow, jo * 2 + lsel);
                ldm4t(vh[jo], vd);
                ldm4t(vl[jo], vd + AKV_B);
            }
            #pragma unroll
            for (int jo = 0; jo < 4; jo++) {
                mma_bf16(O[jo * 2 + 0], pah[t], vh[jo][0], vh[jo][1]);
                mma_bf16(O[jo * 2 + 1], pah[t], vh[jo][2], vh[jo][3]);
            }
            #pragma unroll
            for (int jo = 0; jo < 4; jo++) {
                mma_bf16(O[jo * 2 + 0], pah[t], vl[jo][0], vl[jo][1]);
                mma_bf16(O[jo * 2 + 1], pah[t], vl[jo][2], vl[jo][3]);
            }
            #pragma unroll
            for (int jo = 0; jo < 4; jo++) {
                mma_bf16(O[jo * 2 + 0], pal[t], vh[jo][0], vh[jo][1]);
                mma_bf16(O[jo * 2 + 1], pal[t], vh[jo][2], vh[jo][3]);
            }
        }
        __syncthreads();
    }

    l0r += __shfl_xor_sync(0xffffffffu, l0r, 1);
    l0r += __shfl_xor_sync(0xffffffffu, l0r, 2);
    l1r += __shfl_xor_sync(0xffffffffu, l1r, 1);
    l1r += __shfl_xor_sync(0xffffffffu, l1r, 2);
    const float inv0 = 1.0f / l0r, inv1 = 1.0f / l1r;

    const int row0 = qrow0 + wid * 16 + ldv;
    #pragma unroll
    for (int jn = 0; jn < 8; jn++) {
        const int col = h * DKd + jn * 8 + lam * 2;
        #pragma unroll
        for (int half = 0; half < 2; half++) {
            const float inv = half ? inv1 : inv0;
            const float v0 = O[jn][half * 2 + 0] * inv;
            const float v1 = O[jn][half * 2 + 1] * inv;
            const size_t o = (size_t)b * Sd * Dd +
                             (size_t)(row0 + half * 8) * Dd + col;
            __nv_bfloat16 h0 = __float2bfloat16(v0);
            __nv_bfloat16 h1 = __float2bfloat16(v1);
            __nv_bfloat162 hp; hp.x = h0; hp.y = h1;
            *(__nv_bfloat162*)(Oh + o) = hp;
            __nv_bfloat162 lp;
            lp.x = __float2bfloat16(v0 - __bfloat162float(h0));
            lp.y = __float2bfloat16(v1 - __bfloat162float(h1));
            *(__nv_bfloat162*)(Ol + o) = lp;
        }
    }
}

// ---------------- orchestration --------------------------------------------
extern "C" void kernel_launch(void* const* d_in, const int* in_sizes, int n_in,
                              void* d_out, int out_size) {
    const float* x      = (const float*)d_in[0];
    const int*   mask   = (const int*)  d_in[1];
    const float* wq     = (const float*)d_in[2];
    const float* bq     = (const float*)d_in[3];
    const float* wk     = (const float*)d_in[4];
    const float* bk     = (const float*)d_in[5];
    const float* wv     = (const float*)d_in[6];
    const float* bv     = (const float*)d_in[7];
    const float* wo     = (const float*)d_in[8];
    const float* bo     = (const float*)d_in[9];
    const float* w1     = (const float*)d_in[10];
    const float* b1     = (const float*)d_in[11];
    const float* w2     = (const float*)d_in[12];
    const float* b2     = (const float*)d_in[13];
    const float* alpha1 = (const float*)d_in[14];
    const float* beta1  = (const float*)d_in[15];
    const float* alpha2 = (const float*)d_in[16];
    const float* beta2  = (const float*)d_in[17];
    float* out = (float*)d_out;

    float *x2, *bqkv;
    __nv_bfloat16 *xn_h, *xn_l, *xn2_h, *xn2_l, *ctx_h, *ctx_l;
    __nv_bfloat16 *qkv_h, *qkv_l, *wqkvT_h, *wqkvT_l;
    __nv_bfloat16 *woT_h, *woT_l, *w1T_h, *w1T_l, *w2T_h, *w2T_l, *ff_h, *ff_l;
    cudaGetSymbolAddress((void**)&x2, g_x2);
    cudaGetSymbolAddress((void**)&bqkv, g_bqkv);
    cudaGetSymbolAddress((void**)&xn_h, g_xn_h);   cudaGetSymbolAddress((void**)&xn_l, g_xn_l);
    cudaGetSymbolAddress((void**)&xn2_h, g_xn2_h); cudaGetSymbolAddress((void**)&xn2_l, g_xn2_l);
    cudaGetSymbolAddress((void**)&ctx_h, g_ctx_h); cudaGetSymbolAddress((void**)&ctx_l, g_ctx_l);
    cudaGetSymbolAddress((void**)&qkv_h, g_qkv_h); cudaGetSymbolAddress((void**)&qkv_l, g_qkv_l);
    cudaGetSymbolAddress((void**)&wqkvT_h, g_wqkvT_h);
    cudaGetSymbolAddress((void**)&wqkvT_l, g_wqkvT_l);
    cudaGetSymbolAddress((void**)&woT_h, g_woT_h); cudaGetSymbolAddress((void**)&woT_l, g_woT_l);
    cudaGetSymbolAddress((void**)&w1T_h, g_w1T_h); cudaGetSymbolAddress((void**)&w1T_l, g_w1T_l);
    cudaGetSymbolAddress((void**)&w2T_h, g_w2T_h); cudaGetSymbolAddress((void**)&w2T_l, g_w2T_l);
    cudaGetSymbolAddress((void**)&ff_h, g_ff_h);   cudaGetSymbolAddress((void**)&ff_l, g_ff_l);

    cudaFuncSetAttribute(mma_gemm<1>, cudaFuncAttributeMaxDynamicSharedMemorySize, GEMM_SMEM);
    cudaFuncSetAttribute(mma_gemm<2>, cudaFuncAttributeMaxDynamicSharedMemorySize, GEMM_SMEM);
    cudaFuncSetAttribute(mma_gemm<3>, cudaFuncAttributeMaxDynamicSharedMemorySize, GEMM_SMEM);
    cudaFuncSetAttribute(attn_mma, cudaFuncAttributeMaxDynamicSharedMemorySize, AT_SMEM);

    dim3 tb(32, 8);
    // launches 0-4 (so that launch index 5 = QKV GEMM gets profiled)
    concat3<<<12, 256>>>(bq, bk, bv, bqkv);
    transpose_split<<<dim3(Dd / 32, Dd / 32), tb>>>(wq, wqkvT_h + 0 * Dd * Dd,
                                                    wqkvT_l + 0 * Dd * Dd, Dd, Dd);
    transpose_split<<<dim3(Dd / 32, Dd / 32), tb>>>(wk, wqkvT_h + 1 * Dd * Dd,
                                                    wqkvT_l + 1 * Dd * Dd, Dd, Dd);
    transpose_split<<<dim3(Dd / 32, Dd / 32), tb>>>(wv, wqkvT_h + 2 * Dd * Dd,
                                                    wqkvT_l + 2 * Dd * Dd, Dd, Dd);
    ln_kernel<<<Md, 256>>>(x, xn_h, xn_l, alpha1, beta1);

    // launch 5: fused QKV projection -> packed qkv (hi/lo), N=3072
    mma_gemm<3><<<dim3(NQKV / 128, Md / 128), 256, GEMM_SMEM>>>(
        xn_h, xn_l, wqkvT_h, wqkvT_l, bqkv, nullptr, nullptr,
        qkv_h, qkv_l, Md, NQKV, Dd);

    transpose_split<<<dim3(Dd / 32, Dd / 32), tb>>>(wo, woT_h, woT_l, Dd, Dd);

    // attention -> ctx (hi/lo)
    attn_mma<<<dim3(Sd / 128, Bd * Hd), 256, AT_SMEM>>>(qkv_h, qkv_l, mask,
                                                        ctx_h, ctx_l);

    // O projection + residual -> x2 (f32)
    mma_gemm<1><<<dim3(Dd / 128, Md / 128), 256, GEMM_SMEM>>>(
        ctx_h, ctx_l, woT_h, woT_l, bo, x, x2, nullptr, nullptr, Md, Dd, Dd);

    // LN2 -> xn2 (hi/lo)
    ln_kernel<<<Md, 256>>>(x2, xn2_h, xn2_l, alpha2, beta2);

    transpose_split<<<dim3(DFFd / 32, Dd / 32), tb>>>(w1, w1T_h, w1T_l, Dd, DFFd);

    // FF1 + ReLU -> ff (hi/lo)
    mma_gemm<2><<<dim3(DFFd / 128, Md / 128), 256, GEMM_SMEM>>>(
        xn2_h, xn2_l, w1T_h, w1T_l, b1, nullptr, nullptr, ff_h, ff_l, Md, DFFd, Dd);

    transpose_split<<<dim3(Dd / 32, DFFd / 32), tb>>>(w2, w2T_h, w2T_l, DFFd, Dd);

    // FF2 + residual -> out (f32)
    mma_gemm<1><<<dim3(Dd / 128, Md / 128), 256, GEMM_SMEM>>>(
        ff_h, ff_l, w2T_h, w2T_l, b2, x2, out, nullptr, nullptr, Md, Dd, DFFd);
}

// round 9
// speedup vs baseline: 2.5661x; 1.6033x over previous
#include <cuda_runtime.h>
#include <cuda_fp16.h>
#include <math.h>
#include <stdint.h>
#include <string.h>

#define Bd 4
#define Sd 1024
#define Dd 1024
#define Hd 16
#define DKd 64
#define DFFd 4096
#define Md (Bd * Sd)   // 4096 rows
#define NQKV 3072

// ---------------- scratch (device globals; no runtime allocation) ----------
__device__ float g_x2 [Md * Dd];
__device__ float g_bqkv[NQKV];
__device__ __half g_xn  [Md * Dd];
__device__ __half g_xn2 [Md * Dd];
__device__ __half g_ctx [Md * Dd];
__device__ __half g_qkv_h[(size_t)Md * NQKV], g_qkv_l[(size_t)Md * NQKV];
__device__ __half g_wqkvT_h[NQKV * Dd], g_wqkvT_l[NQKV * Dd];
__device__ __half g_woT_h[Dd * Dd],  g_woT_l[Dd * Dd];
__device__ __half g_w1T_h[DFFd * Dd], g_w1T_l[DFFd * Dd];
__device__ __half g_w2T_h[Dd * DFFd], g_w2T_l[Dd * DFFd];
__device__ __half g_ff  [(size_t)Md * DFFd];

// ---------------- PTX helpers (sm_80-compatible) ----------------------------
__device__ __forceinline__ uint32_t smem_u32(const void* p) {
    uint32_t a;
    asm("{ .reg .u64 t; cvta.to.shared.u64 t, %1; cvt.u32.u64 %0, t; }"
        : "=r"(a) : "l"(p));
    return a;
}
__device__ __forceinline__ void cp16(uint32_t s, const void* g) {
    asm volatile("cp.async.cg.shared.global [%0], [%1], 16;" :: "r"(s), "l"(g));
}
__device__ __forceinline__ void cp_commit() {
    asm volatile("cp.async.commit_group;");
}
template <int N>
__device__ __forceinline__ void cp_wait() {
    asm volatile("cp.async.wait_group %0;" :: "n"(N));
}
__device__ __forceinline__ void ldm4(uint32_t* r, uint32_t a) {
    asm volatile("ldmatrix.sync.aligned.m8n8.x4.shared.b16 {%0,%1,%2,%3}, [%4];"
        : "=r"(r[0]), "=r"(r[1]), "=r"(r[2]), "=r"(r[3]) : "r"(a));
}
__device__ __forceinline__ void ldm4t(uint32_t* r, uint32_t a) {
    asm volatile("ldmatrix.sync.aligned.m8n8.x4.trans.shared.b16 {%0,%1,%2,%3}, [%4];"
        : "=r"(r[0]), "=r"(r[1]), "=r"(r[2]), "=r"(r[3]) : "r"(a));
}
__device__ __forceinline__ void mma_f16(float* d, const uint32_t* a,
                                        uint32_t b0, uint32_t b1) {
    asm volatile(
        "mma.sync.aligned.m16n8k16.row.col.f32.f16.f16.f32 "
        "{%0,%1,%2,%3}, {%4,%5,%6,%7}, {%8,%9}, {%0,%1,%2,%3};"
        : "+f"(d[0]), "+f"(d[1]), "+f"(d[2]), "+f"(d[3])
        : "r"(a[0]), "r"(a[1]), "r"(a[2]), "r"(a[3]), "r"(b0), "r"(b1));
}
__device__ __forceinline__ uint32_t pack_h2(float a, float b) {
    __half2 t = __floats2half2_rn(a, b);
    uint32_t u; memcpy(&u, &t, 4); return u;
}
__device__ __forceinline__ int st_off(int r, int c16) {
    return r * 128 + ((c16 ^ (r & 7)) << 4);   // swizzled byte offset (128B rows)
}

// ---------------- bias concat ------------------------------------------------
__global__ void concat3(const float* __restrict__ a, const float* __restrict__ b,
                        const float* __restrict__ c, float* __restrict__ o) {
    const int i = blockIdx.x * 256 + threadIdx.x;
    if (i < 1024) o[i] = a[i];
    else if (i < 2048) o[i] = b[i - 1024];
    else if (i < 3072) o[i] = c[i - 2048];
}

// ---------------- LayerNorm (torch-style: ddof=1, eps on std) → fp16 --------
__global__ void ln_kernel(const float* __restrict__ X,
                          __half* __restrict__ Y,
                          const float* __restrict__ alpha,
                          const float* __restrict__ beta) {
    __shared__ float red[256];
    __shared__ float s_mean, s_inv;
    const int row = blockIdx.x;
    const int tid = threadIdx.x;
    const float* x = X + (size_t)row * Dd;

    float4 xv = *(const float4*)(x + tid * 4);
    float s = xv.x + xv.y + xv.z + xv.w;
    red[tid] = s; __syncthreads();
    #pragma unroll
    for (int off = 128; off > 0; off >>= 1) {
        if (tid < off) red[tid] += red[tid + off];
        __syncthreads();
    }
    if (tid == 0) s_mean = red[0] * (1.0f / Dd);
    __syncthreads();
    const float mean = s_mean;
    float d0 = xv.x - mean, d1 = xv.y - mean, d2 = xv.z - mean, d3 = xv.w - mean;
    red[tid] = d0 * d0 + d1 * d1 + d2 * d2 + d3 * d3; __syncthreads();
    #pragma unroll
    for (int off = 128; off > 0; off >>= 1) {
        if (tid < off) red[tid] += red[tid + off];
        __syncthreads();
    }
    if (tid == 0) {
        float var = red[0] * (1.0f / (Dd - 1));
        s_inv = alpha[0] / (sqrtf(var) + 1e-6f);
    }
    __syncthreads();
    const float inv = s_inv;
    const float bt  = beta[0];
    size_t o = (size_t)row * Dd + tid * 4;
    *(__half2*)(Y + o + 0) = __floats2half2_rn(d0 * inv + bt, d1 * inv + bt);
    *(__half2*)(Y + o + 2) = __floats2half2_rn(d2 * inv + bt, d3 * inv + bt);
}

// ---------------- weight transpose + fp16 hi/lo split ------------------------
__global__ void transpose_split(const float* __restrict__ in,
                                __half* __restrict__ oh,
                                __half* __restrict__ ol,
                                int R, int C) {
    __shared__ float tile[32][33];
    const int c = blockIdx.x * 32 + threadIdx.x;
    const int r0 = blockIdx.y * 32;
    #pragma unroll
    for (int i = 0; i < 4; i++)
        tile[threadIdx.y + i * 8][threadIdx.x] =
            in[(size_t)(r0 + threadIdx.y + i * 8) * C + c];
    __syncthreads();
    const int rr = r0 + threadIdx.x;
    #pragma unroll
    for (int i = 0; i < 4; i++) {
        const int oc = blockIdx.x * 32 + threadIdx.y + i * 8;
        float v = tile[threadIdx.x][threadIdx.y + i * 8];
        __half h = __float2half_rn(v);
        size_t o = (size_t)oc * R + rr;
        oh[o] = h;
        ol[o] = __float2half_rn(v - __half2float(h));
    }
}

// ---------------- fp16 2-pass GEMM, 128x128 tile, BK=64, 2-stage, 2 CTA/SM --
// C[M,N] = A[M,K] @ (Bh+Bl)[N,K]^T   (A single fp16, B split fp16 hi/lo)
// MODE 1: Cf = acc + bias + Rm
// MODE 2: Ch = fp16(relu(acc + bias))
// MODE 3: Ch/Cl = fp16_split(acc + bias)
#define TILE_B 16384
#define STAGE_B (3 * TILE_B)          // A, Bh, Bl = 48KB
#define GEMM_SMEM (2 * STAGE_B)       // 98304

template <int MODE>
__global__ void __launch_bounds__(256, 2)
mma_gemm(const __half* __restrict__ A,
         const __half* __restrict__ Bh, const __half* __restrict__ Bl,
         const float* __restrict__ bias, const float* __restrict__ Rm,
         float* __restrict__ Cf,
         __half* __restrict__ Ch, __half* __restrict__ Cl,
         int M, int N, int K) {
    extern __shared__ char smem[];
    const uint32_t sb = smem_u32(smem);
    const int tid = threadIdx.x;
    const int wid = tid >> 5, lane = tid & 31;
    const int m0 = blockIdx.y * 128;
    const int n0 = blockIdx.x * 128;
    const int wm = (wid >> 2) * 64;
    const int wn = (wid & 3) * 32;

    float acc[4][4][4];
    #pragma unroll
    for (int a = 0; a < 4; a++)
        #pragma unroll
        for (int b = 0; b < 4; b++)
            #pragma unroll
            for (int c = 0; c < 4; c++) acc[a][b][c] = 0.f;

    const int nstg = K >> 6;

    auto load_stage = [&](int t, int s) {
        const int k0 = t << 6;
        #pragma unroll
        for (int i = 0; i < 4; i++) {
            const int chunk = tid + i * 256;
            const int r = chunk >> 3, c = chunk & 7;
            const uint32_t so = sb + (uint32_t)s * STAGE_B + st_off(r, c);
            const size_t ga = (size_t)(m0 + r) * K + k0 + c * 8;
            const size_t gb = (size_t)(n0 + r) * K + k0 + c * 8;
            cp16(so + 0 * TILE_B, A  + ga);
            cp16(so + 1 * TILE_B, Bh + gb);
            cp16(so + 2 * TILE_B, Bl + gb);
        }
        cp_commit();
    };

    load_stage(0, 0);

    const int lrow = lane & 15, lsel = lane >> 4;

    int s = 0;
    for (int t = 0; t < nstg; t++) {
        cp_wait<0>();
        __syncthreads();                           // single barrier per stage
        if (t + 1 < nstg) load_stage(t + 1, s ^ 1);

        const uint32_t stg = sb + (uint32_t)s * STAGE_B;
        #pragma unroll
        for (int kk = 0; kk < 4; kk++) {
            uint32_t af[4][4], bh[2][4], bl[2][4];
            #pragma unroll
            for (int mt = 0; mt < 4; mt++)
                ldm4(af[mt], stg + st_off(wm + mt * 16 + lrow, kk * 2 + lsel));
            #pragma unroll
            for (int g = 0; g < 2; g++) {
                const uint32_t bd = stg + TILE_B +
                                    st_off(wn + g * 16 + lrow, kk * 2 + lsel);
                ldm4(bh[g], bd);
                ldm4(bl[g], bd + TILE_B);
            }
            #pragma unroll
            for (int mt = 0; mt < 4; mt++)
                #pragma unroll
                for (int nt2 = 0; nt2 < 4; nt2++) {
                    const int g = nt2 >> 1, sel = nt2 & 1;
                    mma_f16(acc[mt][nt2], af[mt], bh[g][sel], bh[g][sel + 2]);
                }
            #pragma unroll
            for (int mt = 0; mt < 4; mt++)
                #pragma unroll
                for (int nt2 = 0; nt2 < 4; nt2++) {
                    const int g = nt2 >> 1, sel = nt2 & 1;
                    mma_f16(acc[mt][nt2], af[mt], bl[g][sel], bl[g][sel + 2]);
                }
        }
        s ^= 1;
    }

    const int er = lane >> 2, ec = (lane & 3) * 2;
    #pragma unroll
    for (int mt = 0; mt < 4; mt++) {
        #pragma unroll
        for (int half = 0; half < 2; half++) {
            const int row = m0 + wm + mt * 16 + er + half * 8;
            #pragma unroll
            for (int nt2 = 0; nt2 < 4; nt2++) {
                const int col = n0 + wn + nt2 * 8 + ec;
                float v0 = acc[mt][nt2][half * 2 + 0] + bias[col];
                float v1 = acc[mt][nt2][half * 2 + 1] + bias[col + 1];
                const size_t o = (size_t)row * N + col;
                if (MODE == 2) {
                    v0 = fmaxf(v0, 0.f); v1 = fmaxf(v1, 0.f);
                    *(__half2*)(Ch + o) = __floats2half2_rn(v0, v1);
                } else if (MODE == 3) {
                    __half h0 = __float2half_rn(v0);
                    __half h1 = __float2half_rn(v1);
                    __half2 hp; hp.x = h0; hp.y = h1;
                    *(__half2*)(Ch + o) = hp;
                    *(__half2*)(Cl + o) = __floats2half2_rn(
                        v0 - __half2float(h0), v1 - __half2float(h1));
                } else {
                    v0 += Rm[o]; v1 += Rm[o + 1];
                    *(float2*)(Cf + o) = make_float2(v0, v1);
                }
            }
        }
    }
}

// ---------------- fp16 2-pass flash attention --------------------------------
// packed qkv (row stride 3072): q at +0 (split), k at +1024 (hi), v at +2048 (split)
#define AQ_B  (128 * 128)             // 128 rows x 128B (64 fp16)
#define AKV_B (64 * 128)              // 64 rows x 128B
#define KVSTG (3 * AKV_B)             // K, Vh, Vl
#define AT_SMEM (2 * AQ_B + 2 * KVSTG + Sd * 4)   // 86016

__global__ void __launch_bounds__(256, 2)
attn_mma(const __half* __restrict__ QKVh, const __half* __restrict__ QKVl,
         const int* __restrict__ mask, __half* __restrict__ O_out) {
    extern __shared__ char smem[];
    const uint32_t sb = smem_u32(smem);
    const uint32_t sQh = sb, sQl = sb + AQ_B;
    int* smask = (int*)(smem + 2 * AQ_B + 2 * KVSTG);

    const int tid = threadIdx.x;
    const int wid = tid >> 5, lane = tid & 31;
    const int lrow = lane & 15, lsel = lane >> 4;
    const int lam = lane & 3, ldv = lane >> 2;

    const int qb = blockIdx.x, bh = blockIdx.y;
    const int b = bh >> 4, h = bh & 15;
    const size_t baseQ = (size_t)b * Sd * NQKV + h * DKd;
    const size_t baseK = baseQ + 1024;
    const size_t baseV = baseQ + 2048;
    const int qrow0 = qb * 128;

    #pragma unroll
    for (int i = 0; i < 4; i++) {
        const int chunk = tid + i * 256;
        const int r = chunk >> 3, c = chunk & 7;
        const size_t g = baseQ + (size_t)(qrow0 + r) * NQKV + c * 8;
        cp16(sQh + st_off(r, c), QKVh + g);
        cp16(sQl + st_off(r, c), QKVl + g);
    }
    for (int i = tid; i < Sd; i += 256) smask[i] = mask[b * Sd + i];

    auto load_kv = [&](int kb, int s) {
        const uint32_t st = sb + 2 * AQ_B + (uint32_t)s * KVSTG;
        #pragma unroll
        for (int i = 0; i < 2; i++) {
            const int chunk = tid + i * 256;
            const int r = chunk >> 3, c = chunk & 7;
            const uint32_t so = st_off(r, c);
            const size_t row = (size_t)(kb * 64 + r) * NQKV + c * 8;
            cp16(st + 0 * AKV_B + so, QKVh + baseK + row);
            cp16(st + 1 * AKV_B + so, QKVh + baseV + row);
            cp16(st + 2 * AKV_B + so, QKVl + baseV + row);
        }
        cp_commit();
    };

    load_kv(0, 0);

    float O[8][4];
    #pragma unroll
    for (int j = 0; j < 8; j++)
        #pragma unroll
        for (int c = 0; c < 4; c++) O[j][c] = 0.f;
    float m0r = -1e30f, m1r = -1e30f, l0r = 0.f, l1r = 0.f;

    const int NKB = Sd / 64;
    int s = 0;
    for (int kb = 0; kb < NKB; kb++) {
        cp_wait<0>();
        __syncthreads();                          // single barrier per kv block
        if (kb + 1 < NKB) load_kv(kb + 1, s ^ 1);

        const uint32_t stK  = sb + 2 * AQ_B + (uint32_t)s * KVSTG;
        const uint32_t stVh = stK + AKV_B;

        // ---- S = Q K^T : qh·kh + ql·kh (2 passes) ----
        float Sc[8][4];
        #pragma unroll
        for (int j = 0; j < 8; j++)
            #pragma unroll
            for (int c = 0; c < 4; c++) Sc[j][c] = 0.f;
        #pragma unroll
        for (int kk = 0; kk < 4; kk++) {
            uint32_t qh[4], ql[4], kh[4][4];
            const uint32_t qa = sQh + st_off(wid * 16 + lrow, kk * 2 + lsel);
            ldm4(qh, qa);
            ldm4(ql, qa + AQ_B);
            #pragma unroll
            for (int g = 0; g < 4; g++)
                ldm4(kh[g], stK + st_off(g * 16 + lrow, kk * 2 + lsel));
            #pragma unroll
            for (int j = 0; j < 8; j++) {
                const int g = j >> 1, sel = j & 1;
                mma_f16(Sc[j], qh, kh[g][sel], kh[g][sel + 2]);
            }
            #pragma unroll
            for (int j = 0; j < 8; j++) {
                const int g = j >> 1, sel = j & 1;
                mma_f16(Sc[j], ql, kh[g][sel], kh[g][sel + 2]);
            }
        }

        #pragma unroll
        for (int j = 0; j < 8; j++) {
            const int col = kb * 64 + j * 8 + lam * 2;
            const int mk0 = smask[col], mk1 = smask[col + 1];
            #pragma unroll
            for (int c = 0; c < 4; c++) Sc[j][c] *= 0.125f;
            if (mk0 == 0) { Sc[j][0] = -1e9f; Sc[j][2] = -1e9f; }
            if (mk1 == 0) { Sc[j][1] = -1e9f; Sc[j][3] = -1e9f; }
        }

        float mx0 = -1e30f, mx1 = -1e30f;
        #pragma unroll
        for (int j = 0; j < 8; j++) {
            mx0 = fmaxf(mx0, fmaxf(Sc[j][0], Sc[j][1]));
            mx1 = fmaxf(mx1, fmaxf(Sc[j][2], Sc[j][3]));
        }
        mx0 = fmaxf(mx0, __shfl_xor_sync(0xffffffffu, mx0, 1));
        mx0 = fmaxf(mx0, __shfl_xor_sync(0xffffffffu, mx0, 2));
        mx1 = fmaxf(mx1, __shfl_xor_sync(0xffffffffu, mx1, 1));
        mx1 = fmaxf(mx1, __shfl_xor_sync(0xffffffffu, mx1, 2));
        const float nm0 = fmaxf(m0r, mx0), nm1 = fmaxf(m1r, mx1);
        const float sf0 = __expf(m0r - nm0), sf1 = __expf(m1r - nm1);
        m0r = nm0; m1r = nm1;
        l0r *= sf0; l1r *= sf1;

        uint32_t pa[4][4];
        #pragma unroll
        for (int j = 0; j < 8; j++) {
            float p0 = __expf(Sc[j][0] - nm0);
            float p1 = __expf(Sc[j][1] - nm0);
            float p2 = __expf(Sc[j][2] - nm1);
            float p3 = __expf(Sc[j][3] - nm1);
            l0r += p0 + p1; l1r += p2 + p3;
            const int t = j >> 1, hi = j & 1;
            pa[t][hi * 2 + 0] = pack_h2(p0, p1);
            pa[t][hi * 2 + 1] = pack_h2(p2, p3);
        }

        #pragma unroll
        for (int j = 0; j < 8; j++) {
            O[j][0] *= sf0; O[j][1] *= sf0;
            O[j][2] *= sf1; O[j][3] *= sf1;
        }

        // ---- O += P V : pa·vh + pa·vl (2 passes) ----
        #pragma unroll
        for (int t = 0; t < 4; t++) {
            uint32_t vh[4][4], vl[4][4];
            #pragma unroll
            for (int jo = 0; jo < 4; jo++) {
                const uint32_t vd = stVh + st_off(t * 16 + lrow, jo * 2 + lsel);
                ldm4t(vh[jo], vd);
                ldm4t(vl[jo], vd + AKV_B);
            }
            #pragma unroll
            for (int jo = 0; jo < 4; jo++) {
                mma_f16(O[jo * 2 + 0], pa[t], vh[jo][0], vh[jo][1]);
                mma_f16(O[jo * 2 + 1], pa[t], vh[jo][2], vh[jo][3]);
            }
            #pragma unroll
            for (int jo = 0; jo < 4; jo++) {
                mma_f16(O[jo * 2 + 0], pa[t], vl[jo][0], vl[jo][1]);
                mma_f16(O[jo * 2 + 1], pa[t], vl[jo][2], vl[jo][3]);
            }
        }
        s ^= 1;
    }

    l0r += __shfl_xor_sync(0xffffffffu, l0r, 1);
    l0r += __shfl_xor_sync(0xffffffffu, l0r, 2);
    l1r += __shfl_xor_sync(0xffffffffu, l1r, 1);
    l1r += __shfl_xor_sync(0xffffffffu, l1r, 2);
    const float inv0 = 1.0f / l0r, inv1 = 1.0f / l1r;

    const int row0 = qrow0 + wid * 16 + ldv;
    #pragma unroll
    for (int jn = 0; jn < 8; jn++) {
        const int col = h * DKd + jn * 8 + lam * 2;
        #pragma unroll
        for (int half = 0; half < 2; half++) {
            const float inv = half ? inv1 : inv0;
            const size_t o = (size_t)b * Sd * Dd +
                             (size_t)(row0 + half * 8) * Dd + col;
            *(__half2*)(O_out + o) = __floats2half2_rn(
                O[jn][half * 2 + 0] * inv, O[jn][half * 2 + 1] * inv);
        }
    }
}

// ---------------- orchestration --------------------------------------------
extern "C" void kernel_launch(void* const* d_in, const int* in_sizes, int n_in,
                              void* d_out, int out_size) {
    const float* x      = (const float*)d_in[0];
    const int*   mask   = (const int*)  d_in[1];
    const float* wq     = (const float*)d_in[2];
    const float* bq     = (const float*)d_in[3];
    const float* wk     = (const float*)d_in[4];
    const float* bk     = (const float*)d_in[5];
    const float* wv     = (const float*)d_in[6];
    const float* bv     = (const float*)d_in[7];
    const float* wo     = (const float*)d_in[8];
    const float* bo     = (const float*)d_in[9];
    const float* w1     = (const float*)d_in[10];
    const float* b1     = (const float*)d_in[11];
    const float* w2     = (const float*)d_in[12];
    const float* b2     = (const float*)d_in[13];
    const float* alpha1 = (const float*)d_in[14];
    const float* beta1  = (const float*)d_in[15];
    const float* alpha2 = (const float*)d_in[16];
    const float* beta2  = (const float*)d_in[17];
    float* out = (float*)d_out;

    float *x2, *bqkv;
    __half *xn, *xn2, *ctx, *qkv_h, *qkv_l, *ff;
    __half *wqkvT_h, *wqkvT_l, *woT_h, *woT_l, *w1T_h, *w1T_l, *w2T_h, *w2T_l;
    cudaGetSymbolAddress((void**)&x2, g_x2);
    cudaGetSymbolAddress((void**)&bqkv, g_bqkv);
    cudaGetSymbolAddress((void**)&xn, g_xn);
    cudaGetSymbolAddress((void**)&xn2, g_xn2);
    cudaGetSymbolAddress((void**)&ctx, g_ctx);
    cudaGetSymbolAddress((void**)&qkv_h, g_qkv_h);
    cudaGetSymbolAddress((void**)&qkv_l, g_qkv_l);
    cudaGetSymbolAddress((void**)&ff, g_ff);
    cudaGetSymbolAddress((void**)&wqkvT_h, g_wqkvT_h);
    cudaGetSymbolAddress((void**)&wqkvT_l, g_wqkvT_l);
    cudaGetSymbolAddress((void**)&woT_h, g_woT_h);
    cudaGetSymbolAddress((void**)&woT_l, g_woT_l);
    cudaGetSymbolAddress((void**)&w1T_h, g_w1T_h);
    cudaGetSymbolAddress((void**)&w1T_l, g_w1T_l);
    cudaGetSymbolAddress((void**)&w2T_h, g_w2T_h);
    cudaGetSymbolAddress((void**)&w2T_l, g_w2T_l);

    cudaFuncSetAttribute(mma_gemm<1>, cudaFuncAttributeMaxDynamicSharedMemorySize, GEMM_SMEM);
    cudaFuncSetAttribute(mma_gemm<2>, cudaFuncAttributeMaxDynamicSharedMemorySize, GEMM_SMEM);
    cudaFuncSetAttribute(mma_gemm<3>, cudaFuncAttributeMaxDynamicSharedMemorySize, GEMM_SMEM);
    cudaFuncSetAttribute(attn_mma, cudaFuncAttributeMaxDynamicSharedMemorySize, AT_SMEM);

    dim3 tb(32, 8);
    // launches 0-5 so that launch index 6 = QKV GEMM (profiled by ncu -s 5)
    concat3<<<12, 256>>>(bq, bk, bv, bqkv);                                    // 0
    transpose_split<<<dim3(Dd / 32, Dd / 32), tb>>>(wq, wqkvT_h + 0 * Dd * Dd, // 1
                                                    wqkvT_l + 0 * Dd * Dd, Dd, Dd);
    transpose_split<<<dim3(Dd / 32, Dd / 32), tb>>>(wk, wqkvT_h + 1 * Dd * Dd, // 2
                                                    wqkvT_l + 1 * Dd * Dd, Dd, Dd);
    transpose_split<<<dim3(Dd / 32, Dd / 32), tb>>>(wv, wqkvT_h + 2 * Dd * Dd, // 3
                                                    wqkvT_l + 2 * Dd * Dd, Dd, Dd);
    transpose_split<<<dim3(Dd / 32, Dd / 32), tb>>>(wo, woT_h, woT_l, Dd, Dd); // 4
    ln_kernel<<<Md, 256>>>(x, xn, alpha1, beta1);                              // 5

    // 6: fused QKV projection -> packed qkv (fp16 hi/lo), N=3072
    mma_gemm<3><<<dim3(NQKV / 128, Md / 128), 256, GEMM_SMEM>>>(
        xn, wqkvT_h, wqkvT_l, bqkv, nullptr, nullptr, qkv_h, qkv_l, Md, NQKV, Dd);

    // 7: attention -> ctx (single fp16)
    attn_mma<<<dim3(Sd / 128, Bd * Hd), 256, AT_SMEM>>>(qkv_h, qkv_l, mask, ctx);

    // 8: O projection + residual -> x2 (f32)
    mma_gemm<1><<<dim3(Dd / 128, Md / 128), 256, GEMM_SMEM>>>(
        ctx, woT_h, woT_l, bo, x, x2, nullptr, nullptr, Md, Dd, Dd);

    // 9: LN2 -> xn2 (fp16)
    ln_kernel<<<Md, 256>>>(x2, xn2, alpha2, beta2);

    transpose_split<<<dim3(DFFd / 32, Dd / 32), tb>>>(w1, w1T_h, w1T_l, Dd, DFFd); // 10

    // 11: FF1 + ReLU -> ff (fp16)
    mma_gemm<2><<<dim3(DFFd / 128, Md / 128), 256, GEMM_SMEM>>>(
        xn2, w1T_h, w1T_l, b1, nullptr, nullptr, ff, nullptr, Md, DFFd, Dd);

    transpose_split<<<dim3(Dd / 32, DFFd / 32), tb>>>(w2, w2T_h, w2T_l, DFFd, Dd); // 12

    // 13: FF2 + residual -> out (f32)
    mma_gemm<1><<<dim3(Dd / 128, Md / 128), 256, GEMM_SMEM>>>(
        ff, w2T_h, w2T_l, b2, x2, out, nullptr, nullptr, Md, Dd, DFFd);
}

// round 10
// speedup vs baseline: 4.2915x; 1.6724x over previous
#include <cuda_runtime.h>
#include <cuda_fp16.h>
#include <math.h>
#include <stdint.h>
#include <string.h>

#define Bd 4
#define Sd 1024
#define Dd 1024
#define Hd 16
#define DKd 64
#define DFFd 4096
#define Md (Bd * Sd)   // 4096 rows
#define NQKV 3072

// ---------------- scratch (device globals; no runtime allocation) ----------
__device__ float g_x2 [Md * Dd];
__device__ float g_bqkv[NQKV];
__device__ __half g_xn  [Md * Dd];
__device__ __half g_xn2 [Md * Dd];
__device__ __half g_ctx [Md * Dd];
__device__ __half g_qkv [(size_t)Md * NQKV];
__device__ __half g_wqkvT[NQKV * Dd];
__device__ __half g_woT[Dd * Dd];
__device__ __half g_w1T[DFFd * Dd];
__device__ __half g_w2T[Dd * DFFd];
__device__ __half g_ff  [(size_t)Md * DFFd];

// ---------------- PTX helpers (sm_80-compatible) ----------------------------
__device__ __forceinline__ uint32_t smem_u32(const void* p) {
    uint32_t a;
    asm("{ .reg .u64 t; cvta.to.shared.u64 t, %1; cvt.u32.u64 %0, t; }"
        : "=r"(a) : "l"(p));
    return a;
}
__device__ __forceinline__ void cp16(uint32_t s, const void* g) {
    asm volatile("cp.async.cg.shared.global [%0], [%1], 16;" :: "r"(s), "l"(g));
}
__device__ __forceinline__ void cp_commit() {
    asm volatile("cp.async.commit_group;");
}
template <int N>
__device__ __forceinline__ void cp_wait() {
    asm volatile("cp.async.wait_group %0;" :: "n"(N));
}
__device__ __forceinline__ void ldm4(uint32_t* r, uint32_t a) {
    asm volatile("ldmatrix.sync.aligned.m8n8.x4.shared.b16 {%0,%1,%2,%3}, [%4];"
        : "=r"(r[0]), "=r"(r[1]), "=r"(r[2]), "=r"(r[3]) : "r"(a));
}
__device__ __forceinline__ void ldm4t(uint32_t* r, uint32_t a) {
    asm volatile("ldmatrix.sync.aligned.m8n8.x4.trans.shared.b16 {%0,%1,%2,%3}, [%4];"
        : "=r"(r[0]), "=r"(r[1]), "=r"(r[2]), "=r"(r[3]) : "r"(a));
}
__device__ __forceinline__ void mma_f16(float* d, const uint32_t* a,
                                        uint32_t b0, uint32_t b1) {
    asm volatile(
        "mma.sync.aligned.m16n8k16.row.col.f32.f16.f16.f32 "
        "{%0,%1,%2,%3}, {%4,%5,%6,%7}, {%8,%9}, {%0,%1,%2,%3};"
        : "+f"(d[0]), "+f"(d[1]), "+f"(d[2]), "+f"(d[3])
        : "r"(a[0]), "r"(a[1]), "r"(a[2]), "r"(a[3]), "r"(b0), "r"(b1));
}
__device__ __forceinline__ uint32_t pack_h2(float a, float b) {
    __half2 t = __floats2half2_rn(a, b);
    uint32_t u; memcpy(&u, &t, 4); return u;
}
__device__ __forceinline__ int st_off(int r, int c16) {
    return r * 128 + ((c16 ^ (r & 7)) << 4);   // swizzled byte offset (128B rows)
}

// ---------------- bias concat ------------------------------------------------
__global__ void concat3(const float* __restrict__ a, const float* __restrict__ b,
                        const float* __restrict__ c, float* __restrict__ o) {
    const int i = blockIdx.x * 256 + threadIdx.x;
    if (i < 1024) o[i] = a[i];
    else if (i < 2048) o[i] = b[i - 1024];
    else if (i < 3072) o[i] = c[i - 2048];
}

// ---------------- fused weight prep: transpose all 6 weights -> fp16 ---------
// flat 32x32 tiles: [0,3072)=wq/wk/wv, [3072,4096)=wo, [4096,8192)=w1, [8192,12288)=w2
__global__ void prep_weights(const float* __restrict__ wq, const float* __restrict__ wk,
                             const float* __restrict__ wv, const float* __restrict__ wo,
                             const float* __restrict__ w1, const float* __restrict__ w2,
                             __half* __restrict__ wqkvT, __half* __restrict__ woT,
                             __half* __restrict__ w1T, __half* __restrict__ w2T) {
    __shared__ float tile[32][33];
    int t = blockIdx.x;
    const float* src; __half* dst; int R, C;
    if (t < 3072) {
        const int m = t / 1024; t -= m * 1024;
        src = (m == 0) ? wq : ((m == 1) ? wk : wv);
        dst = wqkvT + (size_t)m * Dd * Dd; R = Dd; C = Dd;
    } else if (t < 4096) { t -= 3072; src = wo; dst = woT; R = Dd;   C = Dd;  }
    else if (t < 8192)   { t -= 4096; src = w1; dst = w1T; R = Dd;   C = DFFd;}
    else                 { t -= 8192; src = w2; dst = w2T; R = DFFd; C = Dd;  }
    const int ntx = C >> 5;
    const int tc = t % ntx, tr = t / ntx;
    const int c = tc * 32 + threadIdx.x;
    const int r0 = tr * 32;
    #pragma unroll
    for (int i = 0; i < 4; i++)
        tile[threadIdx.y + i * 8][threadIdx.x] =
            src[(size_t)(r0 + threadIdx.y + i * 8) * C + c];
    __syncthreads();
    const int rr = r0 + threadIdx.x;
    #pragma unroll
    for (int i = 0; i < 4; i++) {
        const int oc = tc * 32 + threadIdx.y + i * 8;
        dst[(size_t)oc * R + rr] = __float2half_rn(tile[threadIdx.x][threadIdx.y + i * 8]);
    }
}

// ---------------- LayerNorm (torch-style: ddof=1, eps on std) → fp16 --------
__global__ void ln_kernel(const float* __restrict__ X,
                          __half* __restrict__ Y,
                          const float* __restrict__ alpha,
                          const float* __restrict__ beta) {
    __shared__ float red[256];
    __shared__ float s_mean, s_inv;
    const int row = blockIdx.x;
    const int tid = threadIdx.x;
    const float* x = X + (size_t)row * Dd;

    float4 xv = *(const float4*)(x + tid * 4);
    float s = xv.x + xv.y + xv.z + xv.w;
    red[tid] = s; __syncthreads();
    #pragma unroll
    for (int off = 128; off > 0; off >>= 1) {
        if (tid < off) red[tid] += red[tid + off];
        __syncthreads();
    }
    if (tid == 0) s_mean = red[0] * (1.0f / Dd);
    __syncthreads();
    const float mean = s_mean;
    float d0 = xv.x - mean, d1 = xv.y - mean, d2 = xv.z - mean, d3 = xv.w - mean;
    red[tid] = d0 * d0 + d1 * d1 + d2 * d2 + d3 * d3; __syncthreads();
    #pragma unroll
    for (int off = 128; off > 0; off >>= 1) {
        if (tid < off) red[tid] += red[tid + off];
        __syncthreads();
    }
    if (tid == 0) {
        float var = red[0] * (1.0f / (Dd - 1));
        s_inv = alpha[0] / (sqrtf(var) + 1e-6f);
    }
    __syncthreads();
    const float inv = s_inv;
    const float bt  = beta[0];
    size_t o = (size_t)row * Dd + tid * 4;
    *(__half2*)(Y + o + 0) = __floats2half2_rn(d0 * inv + bt, d1 * inv + bt);
    *(__half2*)(Y + o + 2) = __floats2half2_rn(d2 * inv + bt, d3 * inv + bt);
}

// ---------------- fp16 single-pass GEMM, 128x128, BK=64, 2-stage, 2 CTA/SM --
// MODE 0: Ch = fp16(acc + bias)
// MODE 1: Cf = acc + bias + Rm
// MODE 2: Ch = fp16(relu(acc + bias))
#define TILE_B 16384
#define STAGE_B (2 * TILE_B)          // A, B = 32KB
#define GEMM_SMEM (2 * STAGE_B)       // 65536

template <int MODE>
__global__ void __launch_bounds__(256, 2)
mma_gemm(const __half* __restrict__ A, const __half* __restrict__ B,
         const float* __restrict__ bias, const float* __restrict__ Rm,
         float* __restrict__ Cf, __half* __restrict__ Ch,
         int M, int N, int K) {
    extern __shared__ char smem[];
    const uint32_t sb = smem_u32(smem);
    const int tid = threadIdx.x;
    const int wid = tid >> 5, lane = tid & 31;
    const int m0 = blockIdx.y * 128;
    const int n0 = blockIdx.x * 128;
    const int wm = (wid >> 2) * 64;
    const int wn = (wid & 3) * 32;

    float acc[4][4][4];
    #pragma unroll
    for (int a = 0; a < 4; a++)
        #pragma unroll
        for (int b = 0; b < 4; b++)
            #pragma unroll
            for (int c = 0; c < 4; c++) acc[a][b][c] = 0.f;

    const int nstg = K >> 6;

    auto load_stage = [&](int t, int s) {
        const int k0 = t << 6;
        #pragma unroll
        for (int i = 0; i < 4; i++) {
            const int chunk = tid + i * 256;
            const int r = chunk >> 3, c = chunk & 7;
            const uint32_t so = sb + (uint32_t)s * STAGE_B + st_off(r, c);
            cp16(so, A + (size_t)(m0 + r) * K + k0 + c * 8);
            cp16(so + TILE_B, B + (size_t)(n0 + r) * K + k0 + c * 8);
        }
        cp_commit();
    };

    load_stage(0, 0);

    const int lrow = lane & 15, lsel = lane >> 4;

    int s = 0;
    for (int t = 0; t < nstg; t++) {
        cp_wait<0>();
        __syncthreads();
        if (t + 1 < nstg) load_stage(t + 1, s ^ 1);

        const uint32_t stg = sb + (uint32_t)s * STAGE_B;
        #pragma unroll
        for (int kk = 0; kk < 4; kk++) {
            uint32_t af[4][4], bf[2][4];
            #pragma unroll
            for (int mt = 0; mt < 4; mt++)
                ldm4(af[mt], stg + st_off(wm + mt * 16 + lrow, kk * 2 + lsel));
            #pragma unroll
            for (int g = 0; g < 2; g++)
                ldm4(bf[g], stg + TILE_B + st_off(wn + g * 16 + lrow, kk * 2 + lsel));
            #pragma unroll
            for (int mt = 0; mt < 4; mt++)
                #pragma unroll
                for (int nt2 = 0; nt2 < 4; nt2++) {
                    const int g = nt2 >> 1, sel = nt2 & 1;
                    mma_f16(acc[mt][nt2], af[mt], bf[g][sel], bf[g][sel + 2]);
                }
        }
        s ^= 1;
    }

    const int er = lane >> 2, ec = (lane & 3) * 2;
    #pragma unroll
    for (int mt = 0; mt < 4; mt++) {
        #pragma unroll
        for (int half = 0; half < 2; half++) {
            const int row = m0 + wm + mt * 16 + er + half * 8;
            #pragma unroll
            for (int nt2 = 0; nt2 < 4; nt2++) {
                const int col = n0 + wn + nt2 * 8 + ec;
                float v0 = acc[mt][nt2][half * 2 + 0] + bias[col];
                float v1 = acc[mt][nt2][half * 2 + 1] + bias[col + 1];
                const size_t o = (size_t)row * N + col;
                if (MODE == 0) {
                    *(__half2*)(Ch + o) = __floats2half2_rn(v0, v1);
                } else if (MODE == 2) {
                    *(__half2*)(Ch + o) = __floats2half2_rn(fmaxf(v0, 0.f),
                                                            fmaxf(v1, 0.f));
                } else {
                    v0 += Rm[o]; v1 += Rm[o + 1];
                    *(float2*)(Cf + o) = make_float2(v0, v1);
                }
            }
        }
    }
}

// ---------------- fp16 single-pass flash attention ---------------------------
// packed qkv (row stride 3072): q at +0, k at +1024, v at +2048
#define AQ_B  (128 * 128)             // 128 rows x 128B (64 fp16)
#define AKV_B (64 * 128)
#define KVSTG (2 * AKV_B)             // K, V
#define AT_SMEM (AQ_B + 2 * KVSTG + Sd * 4)   // 53248

__global__ void __launch_bounds__(256, 2)
attn_mma(const __half* __restrict__ QKV, const int* __restrict__ mask,
         __half* __restrict__ O_out) {
    extern __shared__ char smem[];
    const uint32_t sb = smem_u32(smem);
    const uint32_t sQ = sb;
    int* smask = (int*)(smem + AQ_B + 2 * KVSTG);

    const int tid = threadIdx.x;
    const int wid = tid >> 5, lane = tid & 31;
    const int lrow = lane & 15, lsel = lane >> 4;
    const int lam = lane & 3, ldv = lane >> 2;

    const int qb = blockIdx.x, bh = blockIdx.y;
    const int b = bh >> 4, h = bh & 15;
    const size_t baseQ = (size_t)b * Sd * NQKV + h * DKd;
    const size_t baseK = baseQ + 1024;
    const size_t baseV = baseQ + 2048;
    const int qrow0 = qb * 128;

    #pragma unroll
    for (int i = 0; i < 4; i++) {
        const int chunk = tid + i * 256;
        const int r = chunk >> 3, c = chunk & 7;
        cp16(sQ + st_off(r, c), QKV + baseQ + (size_t)(qrow0 + r) * NQKV + c * 8);
    }
    for (int i = tid; i < Sd; i += 256) smask[i] = mask[b * Sd + i];

    auto load_kv = [&](int kb, int s) {
        const uint32_t st = sb + AQ_B + (uint32_t)s * KVSTG;
        #pragma unroll
        for (int i = 0; i < 2; i++) {
            const int chunk = tid + i * 256;
            const int r = chunk >> 3, c = chunk & 7;
            const uint32_t so = st_off(r, c);
            const size_t row = (size_t)(kb * 64 + r) * NQKV + c * 8;
            cp16(st + so, QKV + baseK + row);
            cp16(st + AKV_B + so, QKV + baseV + row);
        }
        cp_commit();
    };

    load_kv(0, 0);

    float O[8][4];
    #pragma unroll
    for (int j = 0; j < 8; j++)
        #pragma unroll
        for (int c = 0; c < 4; c++) O[j][c] = 0.f;
    float m0r = -1e30f, m1r = -1e30f, l0r = 0.f, l1r = 0.f;

    const int NKB = Sd / 64;
    int s = 0;
    for (int kb = 0; kb < NKB; kb++) {
        cp_wait<0>();
        __syncthreads();
        if (kb + 1 < NKB) load_kv(kb + 1, s ^ 1);

        const uint32_t stK = sb + AQ_B + (uint32_t)s * KVSTG;
        const uint32_t stV = stK + AKV_B;

        // ---- S = Q K^T (single pass) ----
        float Sc[8][4];
        #pragma unroll
        for (int j = 0; j < 8; j++)
            #pragma unroll
            for (int c = 0; c < 4; c++) Sc[j][c] = 0.f;
        #pragma unroll
        for (int kk = 0; kk < 4; kk++) {
            uint32_t qf[4], kf[4][4];
            ldm4(qf, sQ + st_off(wid * 16 + lrow, kk * 2 + lsel));
            #pragma unroll
            for (int g = 0; g < 4; g++)
                ldm4(kf[g], stK + st_off(g * 16 + lrow, kk * 2 + lsel));
            #pragma unroll
            for (int j = 0; j < 8; j++) {
                const int g = j >> 1, sel = j & 1;
                mma_f16(Sc[j], qf, kf[g][sel], kf[g][sel + 2]);
            }
        }

        #pragma unroll
        for (int j = 0; j < 8; j++) {
            const int col = kb * 64 + j * 8 + lam * 2;
            const int mk0 = smask[col], mk1 = smask[col + 1];
            #pragma unroll
            for (int c = 0; c < 4; c++) Sc[j][c] *= 0.125f;
            if (mk0 == 0) { Sc[j][0] = -1e9f; Sc[j][2] = -1e9f; }
            if (mk1 == 0) { Sc[j][1] = -1e9f; Sc[j][3] = -1e9f; }
        }

        float mx0 = -1e30f, mx1 = -1e30f;
        #pragma unroll
        for (int j = 0; j < 8; j++) {
            mx0 = fmaxf(mx0, fmaxf(Sc[j][0], Sc[j][1]));
            mx1 = fmaxf(mx1, fmaxf(Sc[j][2], Sc[j][3]));
        }
        mx0 = fmaxf(mx0, __shfl_xor_sync(0xffffffffu, mx0, 1));
        mx0 = fmaxf(mx0, __shfl_xor_sync(0xffffffffu, mx0, 2));
        mx1 = fmaxf(mx1, __shfl_xor_sync(0xffffffffu, mx1, 1));
        mx1 = fmaxf(mx1, __shfl_xor_sync(0xffffffffu, mx1, 2));
        const float nm0 = fmaxf(m0r, mx0), nm1 = fmaxf(m1r, mx1);
        const float sf0 = __expf(m0r - nm0), sf1 = __expf(m1r - nm1);
        m0r = nm0; m1r = nm1;
        l0r *= sf0; l1r *= sf1;

        uint32_t pa[4][4];
        #pragma unroll
        for (int j = 0; j < 8; j++) {
            float p0 = __expf(Sc[j][0] - nm0);
            float p1 = __expf(Sc[j][1] - nm0);
            float p2 = __expf(Sc[j][2] - nm1);
            float p3 = __expf(Sc[j][3] - nm1);
            l0r += p0 + p1; l1r += p2 + p3;
            const int t = j >> 1, hi = j & 1;
            pa[t][hi * 2 + 0] = pack_h2(p0, p1);
            pa[t][hi * 2 + 1] = pack_h2(p2, p3);
        }

        #pragma unroll
        for (int j = 0; j < 8; j++) {
            O[j][0] *= sf0; O[j][1] *= sf0;
            O[j][2] *= sf1; O[j][3] *= sf1;
        }

        // ---- O += P V (single pass) ----
        #pragma unroll
        for (int t = 0; t < 4; t++) {
            uint32_t vf[4][4];
            #pragma unroll
            for (int jo = 0; jo < 4; jo++)
                ldm4t(vf[jo], stV + st_off(t * 16 + lrow, jo * 2 + lsel));
            #pragma unroll
            for (int jo = 0; jo < 4; jo++) {
                mma_f16(O[jo * 2 + 0], pa[t], vf[jo][0], vf[jo][1]);
                mma_f16(O[jo * 2 + 1], pa[t], vf[jo][2], vf[jo][3]);
            }
        }
        s ^= 1;
    }

    l0r += __shfl_xor_sync(0xffffffffu, l0r, 1);
    l0r += __shfl_xor_sync(0xffffffffu, l0r, 2);
    l1r += __shfl_xor_sync(0xffffffffu, l1r, 1);
    l1r += __shfl_xor_sync(0xffffffffu, l1r, 2);
    const float inv0 = 1.0f / l0r, inv1 = 1.0f / l1r;

    const int row0 = qrow0 + wid * 16 + ldv;
    #pragma unroll
    for (int jn = 0; jn < 8; jn++) {
        const int col = h * DKd + jn * 8 + lam * 2;
        #pragma unroll
        for (int half = 0; half < 2; half++) {
            const float inv = half ? inv1 : inv0;
            const size_t o = (size_t)b * Sd * Dd +
                             (size_t)(row0 + half * 8) * Dd + col;
            *(__half2*)(O_out + o) = __floats2half2_rn(
                O[jn][half * 2 + 0] * inv, O[jn][half * 2 + 1] * inv);
        }
    }
}

// ---------------- orchestration --------------------------------------------
extern "C" void kernel_launch(void* const* d_in, const int* in_sizes, int n_in,
                              void* d_out, int out_size) {
    const float* x      = (const float*)d_in[0];
    const int*   mask   = (const int*)  d_in[1];
    const float* wq     = (const float*)d_in[2];
    const float* bq     = (const float*)d_in[3];
    const float* wk     = (const float*)d_in[4];
    const float* bk     = (const float*)d_in[5];
    const float* wv     = (const float*)d_in[6];
    const float* bv     = (const float*)d_in[7];
    const float* wo     = (const float*)d_in[8];
    const float* bo     = (const float*)d_in[9];
    const float* w1     = (const float*)d_in[10];
    const float* b1     = (const float*)d_in[11];
    const float* w2     = (const float*)d_in[12];
    const float* b2     = (const float*)d_in[13];
    const float* alpha1 = (const float*)d_in[14];
    const float* beta1  = (const float*)d_in[15];
    const float* alpha2 = (const float*)d_in[16];
    const float* beta2  = (const float*)d_in[17];
    float* out = (float*)d_out;

    float *x2, *bqkv;
    __half *xn, *xn2, *ctx, *qkv, *ff, *wqkvT, *woT, *w1T, *w2T;
    cudaGetSymbolAddress((void**)&x2, g_x2);
    cudaGetSymbolAddress((void**)&bqkv, g_bqkv);
    cudaGetSymbolAddress((void**)&xn, g_xn);
    cudaGetSymbolAddress((void**)&xn2, g_xn2);
    cudaGetSymbolAddress((void**)&ctx, g_ctx);
    cudaGetSymbolAddress((void**)&qkv, g_qkv);
    cudaGetSymbolAddress((void**)&ff, g_ff);
    cudaGetSymbolAddress((void**)&wqkvT, g_wqkvT);
    cudaGetSymbolAddress((void**)&woT, g_woT);
    cudaGetSymbolAddress((void**)&w1T, g_w1T);
    cudaGetSymbolAddress((void**)&w2T, g_w2T);

    cudaFuncSetAttribute(mma_gemm<0>, cudaFuncAttributeMaxDynamicSharedMemorySize, GEMM_SMEM);
    cudaFuncSetAttribute(mma_gemm<1>, cudaFuncAttributeMaxDynamicSharedMemorySize, GEMM_SMEM);
    cudaFuncSetAttribute(mma_gemm<2>, cudaFuncAttributeMaxDynamicSharedMemorySize, GEMM_SMEM);
    cudaFuncSetAttribute(attn_mma, cudaFuncAttributeMaxDynamicSharedMemorySize, AT_SMEM);

    // 0: biases
    concat3<<<12, 256>>>(bq, bk, bv, bqkv);
    // 1: all weight transposes fused
    prep_weights<<<12288, dim3(32, 8)>>>(wq, wk, wv, wo, w1, w2,
                                         wqkvT, woT, w1T, w2T);
    // 2: LN1 -> xn (fp16)
    ln_kernel<<<Md, 256>>>(x, xn, alpha1, beta1);

    // 3: fused QKV projection -> packed qkv (fp16), N=3072
    mma_gemm<0><<<dim3(NQKV / 128, Md / 128), 256, GEMM_SMEM>>>(
        xn, wqkvT, bqkv, nullptr, nullptr, qkv, Md, NQKV, Dd);

    // 4: attention -> ctx (fp16)
    attn_mma<<<dim3(Sd / 128, Bd * Hd), 256, AT_SMEM>>>(qkv, mask, ctx);

    // 5: O projection + residual -> x2 (f32)
    mma_gemm<1><<<dim3(Dd / 128, Md / 128), 256, GEMM_SMEM>>>(
        ctx, woT, bo, x, x2, nullptr, Md, Dd, Dd);

    // 6: LN2 -> xn2 (fp16)
    ln_kernel<<<Md, 256>>>(x2, xn2, alpha2, beta2);

    // 7: FF1 + ReLU -> ff (fp16)
    mma_gemm<2><<<dim3(DFFd / 128, Md / 128), 256, GEMM_SMEM>>>(
        xn2, w1T, b1, nullptr, nullptr, ff, Md, DFFd, Dd);

    // 8: FF2 + residual -> out (f32)
    mma_gemm<1><<<dim3(Dd / 128, Md / 128), 256, GEMM_SMEM>>>(
        ff, w2T, b2, x2, out, nullptr, Md, Dd, DFFd);
}

// round 15
// speedup vs baseline: 4.3743x; 1.0193x over previous
#include <cuda_runtime.h>
#include <cuda_fp16.h>
#include <math.h>
#include <stdint.h>
#include <string.h>

#define Bd 4
#define Sd 1024
#define Dd 1024
#define Hd 16
#define DKd 64
#define DFFd 4096
#define Md (Bd * Sd)   // 4096 rows
#define NQKV 3072

// ---------------- scratch (device globals; no runtime allocation) ----------
__device__ float g_x2 [Md * Dd];
__device__ float g_bqkv[NQKV];
__device__ __half g_xn  [Md * Dd];
__device__ __half g_xn2 [Md * Dd];
__device__ __half g_ctx [Md * Dd];
__device__ __half g_qkv [(size_t)Md * NQKV];
__device__ __half g_wqkvT[NQKV * Dd];
__device__ __half g_woT[Dd * Dd];
__device__ __half g_w1T[DFFd * Dd];
__device__ __half g_w2T[Dd * DFFd];
__device__ __half g_ff  [(size_t)Md * DFFd];

// ---------------- PTX helpers (sm_80-compatible) ----------------------------
__device__ __forceinline__ uint32_t smem_u32(const void* p) {
    uint32_t a;
    asm("{ .reg .u64 t; cvta.to.shared.u64 t, %1; cvt.u32.u64 %0, t; }"
        : "=r"(a) : "l"(p));
    return a;
}
__device__ __forceinline__ void cp16(uint32_t s, const void* g) {
    asm volatile("cp.async.cg.shared.global [%0], [%1], 16;" :: "r"(s), "l"(g));
}
__device__ __forceinline__ void cp_commit() {
    asm volatile("cp.async.commit_group;");
}
template <int N>
__device__ __forceinline__ void cp_wait() {
    asm volatile("cp.async.wait_group %0;" :: "n"(N));
}
__device__ __forceinline__ void ldm4(uint32_t* r, uint32_t a) {
    asm volatile("ldmatrix.sync.aligned.m8n8.x4.shared.b16 {%0,%1,%2,%3}, [%4];"
        : "=r"(r[0]), "=r"(r[1]), "=r"(r[2]), "=r"(r[3]) : "r"(a));
}
__device__ __forceinline__ void ldm4t(uint32_t* r, uint32_t a) {
    asm volatile("ldmatrix.sync.aligned.m8n8.x4.trans.shared.b16 {%0,%1,%2,%3}, [%4];"
        : "=r"(r[0]), "=r"(r[1]), "=r"(r[2]), "=r"(r[3]) : "r"(a));
}
__device__ __forceinline__ void mma_f16(float* d, const uint32_t* a,
                                        uint32_t b0, uint32_t b1) {
    asm volatile(
        "mma.sync.aligned.m16n8k16.row.col.f32.f16.f16.f32 "
        "{%0,%1,%2,%3}, {%4,%5,%6,%7}, {%8,%9}, {%0,%1,%2,%3};"
        : "+f"(d[0]), "+f"(d[1]), "+f"(d[2]), "+f"(d[3])
        : "r"(a[0]), "r"(a[1]), "r"(a[2]), "r"(a[3]), "r"(b0), "r"(b1));
}
__device__ __forceinline__ uint32_t pack_h2(float a, float b) {
    __half2 t = __floats2half2_rn(a, b);
    uint32_t u; memcpy(&u, &t, 4); return u;
}
__device__ __forceinline__ int st_off(int r, int c16) {
    return r * 128 + ((c16 ^ (r & 7)) << 4);   // swizzled byte offset (128B rows)
}

// ---------------- bias concat ------------------------------------------------
__global__ void concat3(const float* __restrict__ a, const float* __restrict__ b,
                        const float* __restrict__ c, float* __restrict__ o) {
    const int i = blockIdx.x * 256 + threadIdx.x;
    if (i < 1024) o[i] = a[i];
    else if (i < 2048) o[i] = b[i - 1024];
    else if (i < 3072) o[i] = c[i - 2048];
}

// ---------------- fused weight prep: transpose all 6 weights -> fp16 ---------
__global__ void prep_weights(const float* __restrict__ wq, const float* __restrict__ wk,
                             const float* __restrict__ wv, const float* __restrict__ wo,
                             const float* __restrict__ w1, const float* __restrict__ w2,
                             __half* __restrict__ wqkvT, __half* __restrict__ woT,
                             __half* __restrict__ w1T, __half* __restrict__ w2T) {
    __shared__ float tile[32][33];
    int t = blockIdx.x;
    const float* src; __half* dst; int R, C;
    if (t < 3072) {
        const int m = t / 1024; t -= m * 1024;
        src = (m == 0) ? wq : ((m == 1) ? wk : wv);
        dst = wqkvT + (size_t)m * Dd * Dd; R = Dd; C = Dd;
    } else if (t < 4096) { t -= 3072; src = wo; dst = woT; R = Dd;   C = Dd;  }
    else if (t < 8192)   { t -= 4096; src = w1; dst = w1T; R = Dd;   C = DFFd;}
    else                 { t -= 8192; src = w2; dst = w2T; R = DFFd; C = Dd;  }
    const int ntx = C >> 5;
    const int tc = t % ntx, tr = t / ntx;
    const int c = tc * 32 + threadIdx.x;
    const int r0 = tr * 32;
    #pragma unroll
    for (int i = 0; i < 4; i++)
        tile[threadIdx.y + i * 8][threadIdx.x] =
            src[(size_t)(r0 + threadIdx.y + i * 8) * C + c];
    __syncthreads();
    const int rr = r0 + threadIdx.x;
    #pragma unroll
    for (int i = 0; i < 4; i++) {
        const int oc = tc * 32 + threadIdx.y + i * 8;
        dst[(size_t)oc * R + rr] = __float2half_rn(tile[threadIdx.x][threadIdx.y + i * 8]);
    }
}

// ---------------- LayerNorm (torch-style: ddof=1, eps on std) → fp16 --------
__global__ void ln_kernel(const float* __restrict__ X,
                          __half* __restrict__ Y,
                          const float* __restrict__ alpha,
                          const float* __restrict__ beta) {
    __shared__ float red[256];
    __shared__ float s_mean, s_inv;
    const int row = blockIdx.x;
    const int tid = threadIdx.x;
    const float* x = X + (size_t)row * Dd;

    float4 xv = *(const float4*)(x + tid * 4);
    float s = xv.x + xv.y + xv.z + xv.w;
    red[tid] = s; __syncthreads();
    #pragma unroll
    for (int off = 128; off > 0; off >>= 1) {
        if (tid < off) red[tid] += red[tid + off];
        __syncthreads();
    }
    if (tid == 0) s_mean = red[0] * (1.0f / Dd);
    __syncthreads();
    const float mean = s_mean;
    float d0 = xv.x - mean, d1 = xv.y - mean, d2 = xv.z - mean, d3 = xv.w - mean;
    red[tid] = d0 * d0 + d1 * d1 + d2 * d2 + d3 * d3; __syncthreads();
    #pragma unroll
    for (int off = 128; off > 0; off >>= 1) {
        if (tid < off) red[tid] += red[tid + off];
        __syncthreads();
    }
    if (tid == 0) {
        float var = red[0] * (1.0f / (Dd - 1));
        s_inv = alpha[0] / (sqrtf(var) + 1e-6f);
    }
    __syncthreads();
    const float inv = s_inv;
    const float bt  = beta[0];
    size_t o = (size_t)row * Dd + tid * 4;
    *(__half2*)(Y + o + 0) = __floats2half2_rn(d0 * inv + bt, d1 * inv + bt);
    *(__half2*)(Y + o + 2) = __floats2half2_rn(d2 * inv + bt, d3 * inv + bt);
}

// ---------------- fp16 GEMM, 128x128 tile, 4 warps (64x64/warp), BK=64 ------
// 128 threads, 2 CTA/SM. mma:LDSM ratio 32:8.
// MODE 0: Ch = fp16(acc + bias)
// MODE 1: Cf = acc + bias + Rm
// MODE 2: Ch = fp16(relu(acc + bias))
#define TILE_B 16384
#define STAGE_B (2 * TILE_B)          // A, B = 32KB
#define GEMM_SMEM (2 * STAGE_B)       // 65536

template <int MODE>
__global__ void __launch_bounds__(128, 2)
mma_gemm(const __half* __restrict__ A, const __half* __restrict__ B,
         const float* __restrict__ bias, const float* __restrict__ Rm,
         float* __restrict__ Cf, __half* __restrict__ Ch,
         int M, int N, int K) {
    extern __shared__ char smem[];
    const uint32_t sb = smem_u32(smem);
    const int tid = threadIdx.x;
    const int wid = tid >> 5, lane = tid & 31;
    const int m0 = blockIdx.y * 128;
    const int n0 = blockIdx.x * 128;
    const int wm = (wid >> 1) * 64;       // 2x2 warp grid
    const int wn = (wid & 1) * 64;

    float acc[4][8][4];
    #pragma unroll
    for (int a = 0; a < 4; a++)
        #pragma unroll
        for (int b = 0; b < 8; b++)
            #pragma unroll
            for (int c = 0; c < 4; c++) acc[a][b][c] = 0.f;

    const int nstg = K >> 6;

    // 128x64 fp16 tile = 1024 8-elem chunks; each iter loads one A + one B chunk.
    auto load_stage = [&](int t, int s) {
        const int k0 = t << 6;
        #pragma unroll
        for (int i = 0; i < 8; i++) {
            const int chunk = tid + i * 128;           // 0..1023
            const int r = chunk >> 3, c = chunk & 7;
            const uint32_t so = sb + (uint32_t)s * STAGE_B + st_off(r, c);
            cp16(so, A + (size_t)(m0 + r) * K + k0 + c * 8);
            cp16(so + TILE_B, B + (size_t)(n0 + r) * K + k0 + c * 8);
        }
        cp_commit();
    };

    load_stage(0, 0);

    const int lrow = lane & 15, lsel = lane >> 4;

    int s = 0;
    for (int t = 0; t < nstg; t++) {
        cp_wait<0>();
        __syncthreads();
        if (t + 1 < nstg) load_stage(t + 1, s ^ 1);

        const uint32_t stg = sb + (uint32_t)s * STAGE_B;
        #pragma unroll
        for (int kk = 0; kk < 4; kk++) {
            uint32_t af[4][4], bf[4][4];
            #pragma unroll
            for (int mt = 0; mt < 4; mt++)
                ldm4(af[mt], stg + st_off(wm + mt * 16 + lrow, kk * 2 + lsel));
            #pragma unroll
            for (int g = 0; g < 4; g++)
                ldm4(bf[g], stg + TILE_B + st_off(wn + g * 16 + lrow, kk * 2 + lsel));
            #pragma unroll
            for (int mt = 0; mt < 4; mt++)
                #pragma unroll
                for (int nt = 0; nt < 8; nt++) {
                    const int g = nt >> 1, sel = nt & 1;
                    mma_f16(acc[mt][nt], af[mt], bf[g][sel], bf[g][sel + 2]);
                }
        }
        s ^= 1;
    }

    const int er = lane >> 2, ec = (lane & 3) * 2;
    #pragma unroll
    for (int mt = 0; mt < 4; mt++) {
        #pragma unroll
        for (int half = 0; half < 2; half++) {
            const int row = m0 + wm + mt * 16 + er + half * 8;
            #pragma unroll
            for (int nt = 0; nt < 8; nt++) {
                const int col = n0 + wn + nt * 8 + ec;
                float v0 = acc[mt][nt][half * 2 + 0] + bias[col];
                float v1 = acc[mt][nt][half * 2 + 1] + bias[col + 1];
                const size_t o = (size_t)row * N + col;
                if (MODE == 0) {
                    *(__half2*)(Ch + o) = __floats2half2_rn(v0, v1);
                } else if (MODE == 2) {
                    *(__half2*)(Ch + o) = __floats2half2_rn(fmaxf(v0, 0.f),
                                                            fmaxf(v1, 0.f));
                } else {
                    v0 += Rm[o]; v1 += Rm[o + 1];
                    *(float2*)(Cf + o) = make_float2(v0, v1);
                }
            }
        }
    }
}

// ---------------- fp16 single-pass flash attention ---------------------------
// packed qkv (row stride 3072): q at +0, k at +1024, v at +2048
#define AQ_B  (128 * 128)             // 128 rows x 128B (64 fp16)
#define AKV_B (64 * 128)
#define KVSTG (2 * AKV_B)             // K, V
#define AT_SMEM (AQ_B + 2 * KVSTG + Sd * 4)   // 53248

__global__ void __launch_bounds__(256, 2)
attn_mma(const __half* __restrict__ QKV, const int* __restrict__ mask,
         __half* __restrict__ O_out) {
    extern __shared__ char smem[];
    const uint32_t sb = smem_u32(smem);
    const uint32_t sQ = sb;
    int* smask = (int*)(smem + AQ_B + 2 * KVSTG);

    const int tid = threadIdx.x;
    const int wid = tid >> 5, lane = tid & 31;
    const int lrow = lane & 15, lsel = lane >> 4;
    const int lam = lane & 3, ldv = lane >> 2;

    const int qb = blockIdx.x, bh = blockIdx.y;
    const int b = bh >> 4, h = bh & 15;
    const size_t baseQ = (size_t)b * Sd * NQKV + h * DKd;
    const size_t baseK = baseQ + 1024;
    const size_t baseV = baseQ + 2048;
    const int qrow0 = qb * 128;

    #pragma unroll
    for (int i = 0; i < 4; i++) {
        const int chunk = tid + i * 256;
        const int r = chunk >> 3, c = chunk & 7;
        cp16(sQ + st_off(r, c), QKV + baseQ + (size_t)(qrow0 + r) * NQKV + c * 8);
    }
    for (int i = tid; i < Sd; i += 256) smask[i] = mask[b * Sd + i];

    auto load_kv = [&](int kb, int s) {
        const uint32_t st = sb + AQ_B + (uint32_t)s * KVSTG;
        #pragma unroll
        for (int i = 0; i < 2; i++) {
            const int chunk = tid + i * 256;
            const int r = chunk >> 3, c = chunk & 7;
            const uint32_t so = st_off(r, c);
            const size_t row = (size_t)(kb * 64 + r) * NQKV + c * 8;
            cp16(st + so, QKV + baseK + row);
            cp16(st + AKV_B + so, QKV + baseV + row);
        }
        cp_commit();
    };

    load_kv(0, 0);

    float O[8][4];
    #pragma unroll
    for (int j = 0; j < 8; j++)
        #pragma unroll
        for (int c = 0; c < 4; c++) O[j][c] = 0.f;
    float m0r = -1e30f, m1r = -1e30f, l0r = 0.f, l1r = 0.f;

    const int NKB = Sd / 64;
    int s = 0;
    for (int kb = 0; kb < NKB; kb++) {
        cp_wait<0>();
        __syncthreads();
        if (kb + 1 < NKB) load_kv(kb + 1, s ^ 1);

        const uint32_t stK = sb + AQ_B + (uint32_t)s * KVSTG;
        const uint32_t stV = stK + AKV_B;

        float Sc[8][4];
        #pragma unroll
        for (int j = 0; j < 8; j++)
            #pragma unroll
            for (int c = 0; c < 4; c++) Sc[j][c] = 0.f;
        #pragma unroll
        for (int kk = 0; kk < 4; kk++) {
            uint32_t qf[4], kf[4][4];
            ldm4(qf, sQ + st_off(wid * 16 + lrow, kk * 2 + lsel));
            #pragma unroll
            for (int g = 0; g < 4; g++)
                ldm4(kf[g], stK + st_off(g * 16 + lrow, kk * 2 + lsel));
            #pragma unroll
            for (int j = 0; j < 8; j++) {
                const int g = j >> 1, sel = j & 1;
                mma_f16(Sc[j], qf, kf[g][sel], kf[g][sel + 2]);
            }
        }

        #pragma unroll
        for (int j = 0; j < 8; j++) {
            const int col = kb * 64 + j * 8 + lam * 2;
            const int mk0 = smask[col], mk1 = smask[col + 1];
            #pragma unroll
            for (int c = 0; c < 4; c++) Sc[j][c] *= 0.125f;
            if (mk0 == 0) { Sc[j][0] = -1e9f; Sc[j][2] = -1e9f; }
            if (mk1 == 0) { Sc[j][1] = -1e9f; Sc[j][3] = -1e9f; }
        }

        float mx0 = -1e30f, mx1 = -1e30f;
        #pragma unroll
        for (int j = 0; j < 8; j++) {
            mx0 = fmaxf(mx0, fmaxf(Sc[j][0], Sc[j][1]));
            mx1 = fmaxf(mx1, fmaxf(Sc[j][2], Sc[j][3]));
        }
        mx0 = fmaxf(mx0, __shfl_xor_sync(0xffffffffu, mx0, 1));
        mx0 = fmaxf(mx0, __shfl_xor_sync(0xffffffffu, mx0, 2));
        mx1 = fmaxf(mx1, __shfl_xor_sync(0xffffffffu, mx1, 1));
        mx1 = fmaxf(mx1, __shfl_xor_sync(0xffffffffu, mx1, 2));
        const float nm0 = fmaxf(m0r, mx0), nm1 = fmaxf(m1r, mx1);
        const float sf0 = __expf(m0r - nm0), sf1 = __expf(m1r - nm1);
        m0r = nm0; m1r = nm1;
        l0r *= sf0; l1r *= sf1;

        uint32_t pa[4][4];
        #pragma unroll
        for (int j = 0; j < 8; j++) {
            float p0 = __expf(Sc[j][0] - nm0);
            float p1 = __expf(Sc[j][1] - nm0);
            float p2 = __expf(Sc[j][2] - nm1);
            float p3 = __expf(Sc[j][3] - nm1);
            l0r += p0 + p1; l1r += p2 + p3;
            const int t = j >> 1, hi = j & 1;
            pa[t][hi * 2 + 0] = pack_h2(p0, p1);
            pa[t][hi * 2 + 1] = pack_h2(p2, p3);
        }

        #pragma unroll
        for (int j = 0; j < 8; j++) {
            O[j][0] *= sf0; O[j][1] *= sf0;
            O[j][2] *= sf1; O[j][3] *= sf1;
        }

        #pragma unroll
        for (int t = 0; t < 4; t++) {
            uint32_t vf[4][4];
            #pragma unroll
            for (int jo = 0; jo < 4; jo++)
                ldm4t(vf[jo], stV + st_off(t * 16 + lrow, jo * 2 + lsel));
            #pragma unroll
            for (int jo = 0; jo < 4; jo++) {
                mma_f16(O[jo * 2 + 0], pa[t], vf[jo][0], vf[jo][1]);
                mma_f16(O[jo * 2 + 1], pa[t], vf[jo][2], vf[jo][3]);
            }
        }
        s ^= 1;
    }

    l0r += __shfl_xor_sync(0xffffffffu, l0r, 1);
    l0r += __shfl_xor_sync(0xffffffffu, l0r, 2);
    l1r += __shfl_xor_sync(0xffffffffu, l1r, 1);
    l1r += __shfl_xor_sync(0xffffffffu, l1r, 2);
    const float inv0 = 1.0f / l0r, inv1 = 1.0f / l1r;

    const int row0 = qrow0 + wid * 16 + ldv;
    #pragma unroll
    for (int jn = 0; jn < 8; jn++) {
        const int col = h * DKd + jn * 8 + lam * 2;
        #pragma unroll
        for (int half = 0; half < 2; half++) {
            const float inv = half ? inv1 : inv0;
            const size_t o = (size_t)b * Sd * Dd +
                             (size_t)(row0 + half * 8) * Dd + col;
            *(__half2*)(O_out + o) = __floats2half2_rn(
                O[jn][half * 2 + 0] * inv, O[jn][half * 2 + 1] * inv);
        }
    }
}

// ---------------- orchestration --------------------------------------------
extern "C" void kernel_launch(void* const* d_in, const int* in_sizes, int n_in,
                              void* d_out, int out_size) {
    const float* x      = (const float*)d_in[0];
    const int*   mask   = (const int*)  d_in[1];
    const float* wq     = (const float*)d_in[2];
    const float* bq     = (const float*)d_in[3];
    const float* wk     = (const float*)d_in[4];
    const float* bk     = (const float*)d_in[5];
    const float* wv     = (const float*)d_in[6];
    const float* bv     = (const float*)d_in[7];
    const float* wo     = (const float*)d_in[8];
    const float* bo     = (const float*)d_in[9];
    const float* w1     = (const float*)d_in[10];
    const float* b1     = (const float*)d_in[11];
    const float* w2     = (const float*)d_in[12];
    const float* b2     = (const float*)d_in[13];
    const float* alpha1 = (const float*)d_in[14];
    const float* beta1  = (const float*)d_in[15];
    const float* alpha2 = (const float*)d_in[16];
    const float* beta2  = (const float*)d_in[17];
    float* out = (float*)d_out;

    float *x2, *bqkv;
    __half *xn, *xn2, *ctx, *qkv, *ff, *wqkvT, *woT, *w1T, *w2T;
    cudaGetSymbolAddress((void**)&x2, g_x2);
    cudaGetSymbolAddress((void**)&bqkv, g_bqkv);
    cudaGetSymbolAddress((void**)&xn, g_xn);
    cudaGetSymbolAddress((void**)&xn2, g_xn2);
    cudaGetSymbolAddress((void**)&ctx, g_ctx);
    cudaGetSymbolAddress((void**)&qkv, g_qkv);
    cudaGetSymbolAddress((void**)&ff, g_ff);
    cudaGetSymbolAddress((void**)&wqkvT, g_wqkvT);
    cudaGetSymbolAddress((void**)&woT, g_woT);
    cudaGetSymbolAddress((void**)&w1T, g_w1T);
    cudaGetSymbolAddress((void**)&w2T, g_w2T);

    cudaFuncSetAttribute(mma_gemm<0>, cudaFuncAttributeMaxDynamicSharedMemorySize, GEMM_SMEM);
    cudaFuncSetAttribute(mma_gemm<1>, cudaFuncAttributeMaxDynamicSharedMemorySize, GEMM_SMEM);
    cudaFuncSetAttribute(mma_gemm<2>, cudaFuncAttributeMaxDynamicSharedMemorySize, GEMM_SMEM);
    cudaFuncSetAttribute(attn_mma, cudaFuncAttributeMaxDynamicSharedMemorySize, AT_SMEM);

    // 0: biases
    concat3<<<12, 256>>>(bq, bk, bv, bqkv);
    // 1: all weight transposes fused
    prep_weights<<<12288, dim3(32, 8)>>>(wq, wk, wv, wo, w1, w2,
                                         wqkvT, woT, w1T, w2T);
    // 2: LN1 -> xn (fp16)
    ln_kernel<<<Md, 256>>>(x, xn, alpha1, beta1);

    // 3: fused QKV projection -> packed qkv (fp16), N=3072
    mma_gemm<0><<<dim3(NQKV / 128, Md / 128), 128, GEMM_SMEM>>>(
        xn, wqkvT, bqkv, nullptr, nullptr, qkv, Md, NQKV, Dd);

    // 4: attention -> ctx (fp16)
    attn_mma<<<dim3(Sd / 128, Bd * Hd), 256, AT_SMEM>>>(qkv, mask, ctx);

    // 5: O projection + residual -> x2 (f32)
    mma_gemm<1><<<dim3(Dd / 128, Md / 128), 128, GEMM_SMEM>>>(
        ctx, woT, bo, x, x2, nullptr, Md, Dd, Dd);

    // 6: LN2 -> xn2 (fp16)
    ln_kernel<<<Md, 256>>>(x2, xn2, alpha2, beta2);

    // 7: FF1 + ReLU -> ff (fp16)
    mma_gemm<2><<<dim3(DFFd / 128, Md / 128), 128, GEMM_SMEM>>>(
        xn2, w1T, b1, nullptr, nullptr, ff, Md, DFFd, Dd);

    // 8: FF2 + residual -> out (f32)
    mma_gemm<1><<<dim3(Dd / 128, Md / 128), 128, GEMM_SMEM>>>(
        ff, w2T, b2, x2, out, nullptr, Md, Dd, DFFd);
}